// round 14
// baseline (speedup 1.0000x reference)
#include <cuda_runtime.h>
#include <cuda_bf16.h>
#include <cuda_fp16.h>
#include <cstdint>

#define NN 4096
#define HH 512
#define FF 32
#define KSPLIT 16

// ---------------- scratch (device globals: no allocation allowed) ----------
__device__ float  g_deg[NN];
__device__ float  g_agg1p[KSPLIT * NN * FF];        // K-split partials (8 MB)
__device__ float  g_h2p[(size_t)NN * HH];           // gc2 self-partial fp32 (8 MB)
__device__ float4 g_a4[NN];
__device__ float4 g_b4[NN];
__device__ __nv_bfloat16 g_adjb[(size_t)NN * NN];   // adj bf16 (32 MB)
__device__ __nv_bfloat16 g_h1T[(size_t)HH * NN];    // h1^T bf16 (4 MB)
__device__ __half        g_h1h[(size_t)NN * HH];    // h1 fp16 row-major (4 MB)
__device__ __half        g_agg2h[(size_t)NN * HH];  // agg2 fp16 row-major (4 MB)
__device__ __half        g_h2h[(size_t)NN * HH];    // h2 fp16 row-major (4 MB)
__device__ __nv_bfloat16 g_xTb[(size_t)FF * NN];    // x^T bf16 (0.25 MB)
__device__ __half        g_ws2h[(size_t)HH * HH];   // w_self2 fp16
__device__ __half        g_wn2h[(size_t)HH * HH];   // w_neigh2 fp16
__device__ __half        g_w48h[(size_t)64 * HH];   // head weights fp16

// ---------------- mega-prep: deg + adj->bf16 (vectorized) + conversions -----
__global__ void __launch_bounds__(256) megaprep_kernel(
    const float* __restrict__ adj, __nv_bfloat16* __restrict__ adjb,
    const float* __restrict__ ws2, const float* __restrict__ wn2,
    const float* __restrict__ x,
    const float* __restrict__ w_atom, const float* __restrict__ w_bond) {
    int b = blockIdx.x;
    int tid = threadIdx.x;
    if (b < NN) {
        const float4* row = reinterpret_cast<const float4*>(adj + (size_t)b * NN);
        uint4* brow = reinterpret_cast<uint4*>(adjb + (size_t)b * NN);
        float s = 0.f;
        for (int t = tid; t < NN / 8; t += 256) {
            float4 v0 = row[t * 2];
            float4 v1 = row[t * 2 + 1];
            s += (v0.x + v0.y) + (v0.z + v0.w) + (v1.x + v1.y) + (v1.z + v1.w);
            __nv_bfloat162 p0 = __floats2bfloat162_rn(v0.x, v0.y);
            __nv_bfloat162 p1 = __floats2bfloat162_rn(v0.z, v0.w);
            __nv_bfloat162 p2 = __floats2bfloat162_rn(v1.x, v1.y);
            __nv_bfloat162 p3 = __floats2bfloat162_rn(v1.z, v1.w);
            uint4 pk;
            pk.x = *reinterpret_cast<uint32_t*>(&p0);
            pk.y = *reinterpret_cast<uint32_t*>(&p1);
            pk.z = *reinterpret_cast<uint32_t*>(&p2);
            pk.w = *reinterpret_cast<uint32_t*>(&p3);
            brow[t] = pk;
        }
        #pragma unroll
        for (int off = 16; off > 0; off >>= 1)
            s += __shfl_down_sync(0xffffffffu, s, off);
        __shared__ float red[8];
        if ((tid & 31) == 0) red[tid >> 5] = s;
        __syncthreads();
        if (tid == 0) {
            float t = red[0] + red[1] + red[2] + red[3]
                    + red[4] + red[5] + red[6] + red[7];
            g_deg[b] = fmaxf(t, 1.0f);
        }
    } else if (b < NN + 512) {
        int i = (b - NN) * 256 + tid;
        float2 a = reinterpret_cast<const float2*>(ws2)[i];
        float2 c = reinterpret_cast<const float2*>(wn2)[i];
        reinterpret_cast<__half2*>(g_ws2h)[i] = __floats2half2_rn(a.x, a.y);
        reinterpret_cast<__half2*>(g_wn2h)[i] = __floats2half2_rn(c.x, c.y);
    } else if (b < NN + 1024) {
        int i = (b - NN - 512) * 256 + tid;
        int r = i >> 5, c = i & 31;
        g_xTb[(size_t)c * NN + r] = __float2bfloat16(x[i]);
    } else {
        int i = (b - NN - 1024) * 256 + tid;
        int r = i >> 9, k = i & 511;
        float v;
        if (r < 32)      v = w_atom[r * HH + k];
        else if (r < 36) v = w_bond[(r - 32) * (2 * HH) + k];
        else if (r < 40) v = w_bond[(r - 36) * (2 * HH) + HH + k];
        else             v = 0.f;
        g_w48h[(size_t)r * HH + k] = __float2half(v);
    }
}

// ================= common HMMA helpers =======================================
#define ROWB 72
#define TILE_BYTES (128 * ROWB * 2)
#define BUF_BYTES  (2 * TILE_BYTES)
#define MMA_SMEM_TOTAL (2 * BUF_BYTES)

__device__ __forceinline__ uint32_t smem_u32(const void* p) {
    uint32_t a;
    asm("{ .reg .u64 t; cvta.to.shared.u64 t, %1; cvt.u32.u64 %0, t; }"
        : "=r"(a) : "l"(p));
    return a;
}
__device__ __forceinline__ void cp16(uint32_t saddr, const void* gaddr) {
    asm volatile("cp.async.cg.shared.global [%0], [%1], 16;"
                 :: "r"(saddr), "l"(gaddr));
}
__device__ __forceinline__ void ldmx4(uint32_t* r, uint32_t addr) {
    asm volatile("ldmatrix.sync.aligned.m8n8.x4.shared.b16 {%0,%1,%2,%3}, [%4];"
                 : "=r"(r[0]), "=r"(r[1]), "=r"(r[2]), "=r"(r[3]) : "r"(addr));
}
__device__ __forceinline__ void mma_bf16(float* c, const uint32_t* a, const uint32_t* b) {
    asm volatile(
        "mma.sync.aligned.m16n8k16.row.col.f32.bf16.bf16.f32 "
        "{%0,%1,%2,%3}, {%4,%5,%6,%7}, {%8,%9}, {%0,%1,%2,%3};"
        : "+f"(c[0]), "+f"(c[1]), "+f"(c[2]), "+f"(c[3])
        : "r"(a[0]), "r"(a[1]), "r"(a[2]), "r"(a[3]), "r"(b[0]), "r"(b[1]));
}
__device__ __forceinline__ void mma_fp16(float* c, const uint32_t* a, const uint32_t* b) {
    asm volatile(
        "mma.sync.aligned.m16n8k16.row.col.f32.f16.f16.f32 "
        "{%0,%1,%2,%3}, {%4,%5,%6,%7}, {%8,%9}, {%0,%1,%2,%3};"
        : "+f"(c[0]), "+f"(c[1]), "+f"(c[2]), "+f"(c[3])
        : "r"(a[0]), "r"(a[1]), "r"(a[2]), "r"(a[3]), "r"(b[0]), "r"(b[1]));
}

template <typename T>
__device__ __forceinline__ void stage_tile(uint32_t dst, const T* __restrict__ src,
                                           int row0, int k0, size_t stride, int tid,
                                           int nrows) {
    int per = (nrows * 8) / 256;
    for (int q = 0; q < per; q++) {
        int idx = tid + q * 256;
        int r = idx >> 3, c = idx & 7;
        uint32_t soff = (uint32_t)(r * ROWB + c * 8) * 2;
        cp16(dst + soff, src + (size_t)(row0 + r) * stride + k0 + c * 8);
    }
}

// ---------------- gc1: h1 = relu(x Ws1^T + agg1 Wn1^T + b), K=32 ------------
__global__ void __launch_bounds__(256) fused_gc1_kernel(
    const float* __restrict__ A1, const float* __restrict__ W1, const float* __restrict__ b1,
    const float* __restrict__ P, const float* __restrict__ W2, const float* __restrict__ b2,
    __nv_bfloat16* __restrict__ CT, __half* __restrict__ CH) {
    const int K = FF;
    __shared__ float As1[2][8][128], As2[2][8][128];
    __shared__ float Bs1[2][8][128], Bs2[2][8][128];

    int tid = threadIdx.x, bx = blockIdx.x, by = blockIdx.y;
    int tx = tid & 15, ty = tid >> 4;
    int lRow = tid >> 1, lC = (tid & 1) * 4;

    const float* A1p = A1 + (size_t)(by * 128 + lRow) * K + lC;
    const float* W1p = W1 + (size_t)(bx * 128 + lRow) * K + lC;
    const float* W2p = W2 + (size_t)(bx * 128 + lRow) * K + lC;

    int a2row = by * 128 + lRow;
    size_t a2idx = (size_t)a2row * FF + lC;
    float dinv = 1.0f / g_deg[a2row];

    auto loadA2 = [&](int k) -> float4 {
        float4 s = make_float4(0.f, 0.f, 0.f, 0.f);
        #pragma unroll
        for (int p = 0; p < KSPLIT; p++) {
            float4 v = *(const float4*)(P + (size_t)p * NN * FF + a2idx + k);
            s.x += v.x; s.y += v.y; s.z += v.z; s.w += v.w;
        }
        s.x *= dinv; s.y *= dinv; s.z *= dinv; s.w *= dinv;
        return s;
    };

    float acc[8][8] = {};

    {
        float4 a1 = *(const float4*)A1p;
        float4 a2 = loadA2(0);
        float4 w1 = *(const float4*)W1p;
        float4 w2 = *(const float4*)W2p;
        As1[0][lC + 0][lRow] = a1.x; As1[0][lC + 1][lRow] = a1.y;
        As1[0][lC + 2][lRow] = a1.z; As1[0][lC + 3][lRow] = a1.w;
        As2[0][lC + 0][lRow] = a2.x; As2[0][lC + 1][lRow] = a2.y;
        As2[0][lC + 2][lRow] = a2.z; As2[0][lC + 3][lRow] = a2.w;
        Bs1[0][lC + 0][lRow] = w1.x; Bs1[0][lC + 1][lRow] = w1.y;
        Bs1[0][lC + 2][lRow] = w1.z; Bs1[0][lC + 3][lRow] = w1.w;
        Bs2[0][lC + 0][lRow] = w2.x; Bs2[0][lC + 1][lRow] = w2.y;
        Bs2[0][lC + 2][lRow] = w2.z; Bs2[0][lC + 3][lRow] = w2.w;
    }
    __syncthreads();

    int nIter = K / 8;
    for (int it = 0; it < nIter; ++it) {
        int cur = it & 1;
        float4 na1, na2, nw1, nw2;
        bool more = (it + 1 < nIter);
        if (more) {
            int k = (it + 1) * 8;
            na1 = *(const float4*)(A1p + k);
            na2 = loadA2(k);
            nw1 = *(const float4*)(W1p + k);
            nw2 = *(const float4*)(W2p + k);
        }
        #pragma unroll
        for (int k = 0; k < 8; k++) {
            float ar1[8], ar2[8], wr1[8], wr2[8];
            #pragma unroll
            for (int i = 0; i < 8; i++) { ar1[i] = As1[cur][k][ty * 8 + i]; ar2[i] = As2[cur][k][ty * 8 + i]; }
            #pragma unroll
            for (int j = 0; j < 8; j++) { wr1[j] = Bs1[cur][k][tx * 8 + j]; wr2[j] = Bs2[cur][k][tx * 8 + j]; }
            #pragma unroll
            for (int i = 0; i < 8; i++)
                #pragma unroll
                for (int j = 0; j < 8; j++)
                    acc[i][j] += ar1[i] * wr1[j] + ar2[i] * wr2[j];
        }
        if (more) {
            int nxt = cur ^ 1;
            __syncthreads();
            As1[nxt][lC + 0][lRow] = na1.x; As1[nxt][lC + 1][lRow] = na1.y;
            As1[nxt][lC + 2][lRow] = na1.z; As1[nxt][lC + 3][lRow] = na1.w;
            As2[nxt][lC + 0][lRow] = na2.x; As2[nxt][lC + 1][lRow] = na2.y;
            As2[nxt][lC + 2][lRow] = na2.z; As2[nxt][lC + 3][lRow] = na2.w;
            Bs1[nxt][lC + 0][lRow] = nw1.x; Bs1[nxt][lC + 1][lRow] = nw1.y;
            Bs1[nxt][lC + 2][lRow] = nw1.z; Bs1[nxt][lC + 3][lRow] = nw1.w;
            Bs2[nxt][lC + 0][lRow] = nw2.x; Bs2[nxt][lC + 1][lRow] = nw2.y;
            Bs2[nxt][lC + 2][lRow] = nw2.z; Bs2[nxt][lC + 3][lRow] = nw2.w;
            __syncthreads();
        }
    }

    int row0 = by * 128 + ty * 8;
    int col0 = bx * 128 + tx * 8;
    float bias[8];
    #pragma unroll
    for (int j = 0; j < 8; j++) bias[j] = b1[col0 + j] + b2[col0 + j];
    #pragma unroll
    for (int i = 0; i < 8; i++)
        #pragma unroll
        for (int j = 0; j < 8; j++)
            acc[i][j] = fmaxf(acc[i][j] + bias[j], 0.f);

    #pragma unroll
    for (int i = 0; i < 8; i++) {
        __half hv[8];
        #pragma unroll
        for (int j = 0; j < 8; j++) hv[j] = __float2half(acc[i][j]);
        *(uint4*)&CH[(size_t)(row0 + i) * HH + col0] = *(uint4*)hv;
    }
    #pragma unroll
    for (int j = 0; j < 8; j++) {
        __nv_bfloat16 tv[8];
        #pragma unroll
        for (int i = 0; i < 8; i++) tv[i] = __float2bfloat16(acc[i][j]);
        *(uint4*)&CT[(size_t)(col0 + j) * NN + row0] = *(uint4*)tv;
    }
}

// ================= agg1 partials: K-split x16, single-sync pipeline =========
#define A1_B_TILE (32 * ROWB * 2)
#define A1_BUF (TILE_BYTES + A1_B_TILE)
#define A1_SMEM_TOTAL (2 * A1_BUF)

__global__ void __launch_bounds__(256) mma_agg1_kernel(
    const __nv_bfloat16* __restrict__ Ab, const __nv_bfloat16* __restrict__ Bb,
    float* __restrict__ Pout) {
    extern __shared__ char smem[];
    uint32_t sbase = smem_u32(smem);
    const int tid = threadIdx.x, lane = tid & 31, wm = tid >> 5;
    const int m0 = blockIdx.y * 128;
    const int kbase = blockIdx.x * (NN / KSPLIT);
    float* out = Pout + (size_t)blockIdx.x * NN * FF;

    const int sel = lane >> 3, lr = lane & 7;
    uint32_t a_off = (uint32_t)(((wm * 16 + (sel & 1) * 8 + lr) * ROWB
                                 + (sel >> 1) * 8) * 2);
    uint32_t b_off[2];
    #pragma unroll
    for (int ntp = 0; ntp < 2; ntp++)
        b_off[ntp] = (uint32_t)(TILE_BYTES
                     + ((ntp * 16 + (sel >> 1) * 8 + lr) * ROWB + (sel & 1) * 8) * 2);

    float acc[4][4] = {};

    const int NCHUNK = (NN / KSPLIT) / 64;
    stage_tile(sbase, Ab, m0, kbase, NN, tid, 128);
    stage_tile(sbase + TILE_BYTES, Bb, 0, kbase, NN, tid, 32);
    asm volatile("cp.async.commit_group;" ::: "memory");

    for (int it = 0; it < NCHUNK; ++it) {
        asm volatile("cp.async.wait_group 0;" ::: "memory");
        __syncthreads();
        if (it + 1 < NCHUNK) {
            uint32_t nb = sbase + ((it + 1) & 1) * A1_BUF;
            stage_tile(nb, Ab, m0, kbase + (it + 1) * 64, NN, tid, 128);
            stage_tile(nb + TILE_BYTES, Bb, 0, kbase + (it + 1) * 64, NN, tid, 32);
            asm volatile("cp.async.commit_group;" ::: "memory");
        }
        uint32_t cbase = sbase + (it & 1) * A1_BUF;
        #pragma unroll
        for (int ks = 0; ks < 4; ks++) {
            uint32_t a[4], b[2][4];
            ldmx4(a, cbase + a_off + ks * 32);
            #pragma unroll
            for (int ntp = 0; ntp < 2; ntp++)
                ldmx4(b[ntp], cbase + b_off[ntp] + ks * 32);
            #pragma unroll
            for (int nt = 0; nt < 4; nt++)
                mma_bf16(acc[nt], a, &b[nt >> 1][(nt & 1) * 2]);
        }
    }

    int rg = m0 + wm * 16 + (lane >> 2);
    #pragma unroll
    for (int nt = 0; nt < 4; nt++) {
        int col = nt * 8 + (lane & 3) * 2;
        *(float2*)&out[(size_t)rg * FF + col] = make_float2(acc[nt][0], acc[nt][1]);
        *(float2*)&out[(size_t)(rg + 8) * FF + col] = make_float2(acc[nt][2], acc[nt][3]);
    }
}

// ================= agg2: 64x128 tile, 3-stage, single-sync (R11 proven) =====
#define A2_A_TILE (64 * ROWB * 2)
#define A2_BUF (A2_A_TILE + TILE_BYTES)
#define A2_SMEM_TOTAL (3 * A2_BUF)

__global__ void __launch_bounds__(256) mma_agg2_kernel(
    const __nv_bfloat16* __restrict__ Ab,
    const __nv_bfloat16* __restrict__ Bb,
    __half* __restrict__ Cout) {
    extern __shared__ char smem[];
    uint32_t sbase = smem_u32(smem);

    const int tid = threadIdx.x;
    const int lane = tid & 31, wid = tid >> 5;
    const int wm = wid & 1, wn = wid >> 1;
    const int m0 = blockIdx.y * 64, n0 = blockIdx.x * 128;

    const int sel = lane >> 3, lr = lane & 7;
    uint32_t a_off[2], b_off[2];
    #pragma unroll
    for (int mt = 0; mt < 2; mt++)
        a_off[mt] = (uint32_t)(((wm * 32 + mt * 16 + (sel & 1) * 8 + lr) * ROWB
                                + (sel >> 1) * 8) * 2);
    #pragma unroll
    for (int ntp = 0; ntp < 2; ntp++)
        b_off[ntp] = (uint32_t)(A2_A_TILE
                     + ((wn * 32 + ntp * 16 + (sel >> 1) * 8 + lr) * ROWB
                        + (sel & 1) * 8) * 2);

    float acc[2][4][4] = {};

    const int NCHUNK = NN / 64;
    #pragma unroll
    for (int s = 0; s < 2; s++) {
        uint32_t sb = sbase + s * A2_BUF;
        stage_tile(sb, Ab, m0, s * 64, NN, tid, 64);
        stage_tile(sb + A2_A_TILE, Bb, n0, s * 64, NN, tid, 128);
        asm volatile("cp.async.commit_group;" ::: "memory");
    }

    int slot = 0;
    for (int it = 0; it < NCHUNK; ++it) {
        if (it + 1 < NCHUNK) {
            asm volatile("cp.async.wait_group 1;" ::: "memory");
        } else {
            asm volatile("cp.async.wait_group 0;" ::: "memory");
        }
        __syncthreads();
        if (it + 2 < NCHUNK) {
            int ns = slot + 2; if (ns >= 3) ns -= 3;
            uint32_t nb = sbase + ns * A2_BUF;
            stage_tile(nb, Ab, m0, (it + 2) * 64, NN, tid, 64);
            stage_tile(nb + A2_A_TILE, Bb, n0, (it + 2) * 64, NN, tid, 128);
            asm volatile("cp.async.commit_group;" ::: "memory");
        }

        uint32_t cbase = sbase + slot * A2_BUF;
        #pragma unroll
        for (int ks = 0; ks < 4; ks++) {
            uint32_t a[2][4], b[2][4];
            #pragma unroll
            for (int mt = 0; mt < 2; mt++)
                ldmx4(a[mt], cbase + a_off[mt] + ks * 32);
            #pragma unroll
            for (int ntp = 0; ntp < 2; ntp++)
                ldmx4(b[ntp], cbase + b_off[ntp] + ks * 32);
            #pragma unroll
            for (int mt = 0; mt < 2; mt++)
                #pragma unroll
                for (int nt = 0; nt < 4; nt++)
                    mma_bf16(acc[mt][nt], a[mt], &b[nt >> 1][(nt & 1) * 2]);
        }
        slot = slot + 1; if (slot >= 3) slot -= 3;
    }

    #pragma unroll
    for (int mt = 0; mt < 2; mt++) {
        int rg = m0 + wm * 32 + mt * 16 + (lane >> 2);
        float inv0 = 1.0f / g_deg[rg];
        float inv1 = 1.0f / g_deg[rg + 8];
        #pragma unroll
        for (int nt = 0; nt < 4; nt++) {
            int col = n0 + wn * 32 + nt * 8 + (lane & 3) * 2;
            *(__half2*)&Cout[(size_t)rg * HH + col] =
                __floats2half2_rn(acc[mt][nt][0] * inv0, acc[mt][nt][1] * inv0);
            *(__half2*)&Cout[(size_t)(rg + 8) * HH + col] =
                __floats2half2_rn(acc[mt][nt][2] * inv1, acc[mt][nt][3] * inv1);
        }
    }
}

// ================= gc2a: P = h1h @ ws2^T (fp32 partial), K=512 ===============
__global__ void __launch_bounds__(256) mma_gc2a_kernel(
    const __half* __restrict__ A1, const __half* __restrict__ W1,
    float* __restrict__ Pout) {
    extern __shared__ char smem[];
    uint32_t sbase = smem_u32(smem);

    const int tid = threadIdx.x;
    const int lane = tid & 31, wid = tid >> 5;
    const int wm = wid & 3, wn = wid >> 2;
    const int m0 = blockIdx.y * 128, n0 = blockIdx.x * 128;

    const int sel = lane >> 3, lr = lane & 7;
    uint32_t a_off[2], b_off[4];
    #pragma unroll
    for (int mt = 0; mt < 2; mt++)
        a_off[mt] = (uint32_t)(((wm * 32 + mt * 16 + (sel & 1) * 8 + lr) * ROWB
                                + (sel >> 1) * 8) * 2);
    #pragma unroll
    for (int ntp = 0; ntp < 4; ntp++)
        b_off[ntp] = (uint32_t)(TILE_BYTES
                     + ((wn * 64 + ntp * 16 + (sel >> 1) * 8 + lr) * ROWB
                        + (sel & 1) * 8) * 2);

    float acc[2][8][4] = {};

    const int NCHUNK = 8;
    stage_tile(sbase, A1, m0, 0, HH, tid, 128);
    stage_tile(sbase + TILE_BYTES, W1, n0, 0, HH, tid, 128);
    asm volatile("cp.async.commit_group;" ::: "memory");

    for (int it = 0; it < NCHUNK; ++it) {
        asm volatile("cp.async.wait_group 0;" ::: "memory");
        __syncthreads();
        if (it + 1 < NCHUNK) {
            int k0 = (it + 1) * 64;
            uint32_t nb = sbase + ((it + 1) & 1) * BUF_BYTES;
            stage_tile(nb, A1, m0, k0, HH, tid, 128);
            stage_tile(nb + TILE_BYTES, W1, n0, k0, HH, tid, 128);
            asm volatile("cp.async.commit_group;" ::: "memory");
        }
        uint32_t cbase = sbase + (it & 1) * BUF_BYTES;
        #pragma unroll
        for (int ks = 0; ks < 4; ks++) {
            uint32_t a[2][4], b[4][4];
            #pragma unroll
            for (int mt = 0; mt < 2; mt++)
                ldmx4(a[mt], cbase + a_off[mt] + ks * 32);
            #pragma unroll
            for (int ntp = 0; ntp < 4; ntp++)
                ldmx4(b[ntp], cbase + b_off[ntp] + ks * 32);
            #pragma unroll
            for (int mt = 0; mt < 2; mt++)
                #pragma unroll
                for (int nt = 0; nt < 8; nt++)
                    mma_fp16(acc[mt][nt], a[mt], &b[nt >> 1][(nt & 1) * 2]);
        }
    }

    #pragma unroll
    for (int mt = 0; mt < 2; mt++) {
        int rg = m0 + wm * 32 + mt * 16 + (lane >> 2);
        #pragma unroll
        for (int nt = 0; nt < 8; nt++) {
            int col = n0 + wn * 64 + nt * 8 + (lane & 3) * 2;
            *(float2*)&Pout[(size_t)rg * HH + col] =
                make_float2(acc[mt][nt][0], acc[mt][nt][1]);
            *(float2*)&Pout[(size_t)(rg + 8) * HH + col] =
                make_float2(acc[mt][nt][2], acc[mt][nt][3]);
        }
    }
}

// ================= gc2b: h2 = relu(P + agg2h @ wn2^T + b), K=512 =============
__global__ void __launch_bounds__(256) mma_gc2b_kernel(
    const __half* __restrict__ A2, const __half* __restrict__ W2,
    const float* __restrict__ P,
    const float* __restrict__ b1, const float* __restrict__ b2,
    __half* __restrict__ Cout) {
    extern __shared__ char smem[];
    uint32_t sbase = smem_u32(smem);

    const int tid = threadIdx.x;
    const int lane = tid & 31, wid = tid >> 5;
    const int wm = wid & 3, wn = wid >> 2;
    const int m0 = blockIdx.y * 128, n0 = blockIdx.x * 128;

    const int sel = lane >> 3, lr = lane & 7;
    uint32_t a_off[2], b_off[4];
    #pragma unroll
    for (int mt = 0; mt < 2; mt++)
        a_off[mt] = (uint32_t)(((wm * 32 + mt * 16 + (sel & 1) * 8 + lr) * ROWB
                                + (sel >> 1) * 8) * 2);
    #pragma unroll
    for (int ntp = 0; ntp < 4; ntp++)
        b_off[ntp] = (uint32_t)(TILE_BYTES
                     + ((wn * 64 + ntp * 16 + (sel >> 1) * 8 + lr) * ROWB
                        + (sel & 1) * 8) * 2);

    float acc[2][8][4] = {};

    const int NCHUNK = 8;
    stage_tile(sbase, A2, m0, 0, HH, tid, 128);
    stage_tile(sbase + TILE_BYTES, W2, n0, 0, HH, tid, 128);
    asm volatile("cp.async.commit_group;" ::: "memory");

    for (int it = 0; it < NCHUNK; ++it) {
        asm volatile("cp.async.wait_group 0;" ::: "memory");
        __syncthreads();
        if (it + 1 < NCHUNK) {
            int k0 = (it + 1) * 64;
            uint32_t nb = sbase + ((it + 1) & 1) * BUF_BYTES;
            stage_tile(nb, A2, m0, k0, HH, tid, 128);
            stage_tile(nb + TILE_BYTES, W2, n0, k0, HH, tid, 128);
            asm volatile("cp.async.commit_group;" ::: "memory");
        }
        uint32_t cbase = sbase + (it & 1) * BUF_BYTES;
        #pragma unroll
        for (int ks = 0; ks < 4; ks++) {
            uint32_t a[2][4], b[4][4];
            #pragma unroll
            for (int mt = 0; mt < 2; mt++)
                ldmx4(a[mt], cbase + a_off[mt] + ks * 32);
            #pragma unroll
            for (int ntp = 0; ntp < 4; ntp++)
                ldmx4(b[ntp], cbase + b_off[ntp] + ks * 32);
            #pragma unroll
            for (int mt = 0; mt < 2; mt++)
                #pragma unroll
                for (int nt = 0; nt < 8; nt++)
                    mma_fp16(acc[mt][nt], a[mt], &b[nt >> 1][(nt & 1) * 2]);
        }
    }

    #pragma unroll
    for (int mt = 0; mt < 2; mt++) {
        int rg = m0 + wm * 32 + mt * 16 + (lane >> 2);
        #pragma unroll
        for (int nt = 0; nt < 8; nt++) {
            int col = n0 + wn * 64 + nt * 8 + (lane & 3) * 2;
            float bb0 = b1[col] + b2[col];
            float bb1 = b1[col + 1] + b2[col + 1];
            float2 p0 = *(const float2*)&P[(size_t)rg * HH + col];
            float2 p1 = *(const float2*)&P[(size_t)(rg + 8) * HH + col];
            *(__half2*)&Cout[(size_t)rg * HH + col] =
                __floats2half2_rn(fmaxf(acc[mt][nt][0] + p0.x + bb0, 0.f),
                                  fmaxf(acc[mt][nt][1] + p0.y + bb1, 0.f));
            *(__half2*)&Cout[(size_t)(rg + 8) * HH + col] =
                __floats2half2_rn(fmaxf(acc[mt][nt][2] + p1.x + bb0, 0.f),
                                  fmaxf(acc[mt][nt][3] + p1.y + bb1, 0.f));
        }
    }
}

// ================= head via fp16 HMMA, single-sync ===========================
#define HD_TILE (64 * ROWB * 2)
#define HD_BUF (2 * HD_TILE)
#define HD_SMEM_TOTAL (2 * HD_BUF)

__global__ void __launch_bounds__(256) head_mma_kernel(
    const __half* __restrict__ A, const __half* __restrict__ B,
    const float* __restrict__ b_atom, float* __restrict__ atom_out) {
    extern __shared__ char smem[];
    uint32_t sbase = smem_u32(smem);

    const int tid = threadIdx.x;
    const int lane = tid & 31, wid = tid >> 5;
    const int wm = wid & 1, wn = wid >> 1;
    const int m0 = blockIdx.y * 64;

    const int sel = lane >> 3, lr = lane & 7;
    uint32_t a_off[2];
    #pragma unroll
    for (int mt = 0; mt < 2; mt++)
        a_off[mt] = (uint32_t)(((wm * 32 + mt * 16 + (sel & 1) * 8 + lr) * ROWB
                                + (sel >> 1) * 8) * 2);
    uint32_t b_off = (uint32_t)(HD_TILE
                     + ((wn * 16 + (sel >> 1) * 8 + lr) * ROWB + (sel & 1) * 8) * 2);

    float acc[2][2][4] = {};

    const int NCHUNK = 8;
    stage_tile(sbase, A, m0, 0, HH, tid, 64);
    stage_tile(sbase + HD_TILE, B, 0, 0, HH, tid, 64);
    asm volatile("cp.async.commit_group;" ::: "memory");

    for (int it = 0; it < NCHUNK; ++it) {
        asm volatile("cp.async.wait_group 0;" ::: "memory");
        __syncthreads();
        if (it + 1 < NCHUNK) {
            uint32_t nb = sbase + ((it + 1) & 1) * HD_BUF;
            stage_tile(nb, A, m0, (it + 1) * 64, HH, tid, 64);
            stage_tile(nb + HD_TILE, B, 0, (it + 1) * 64, HH, tid, 64);
            asm volatile("cp.async.commit_group;" ::: "memory");
        }

        uint32_t cbase = sbase + (it & 1) * HD_BUF;
        #pragma unroll
        for (int ks = 0; ks < 4; ks++) {
            uint32_t a[2][4], b[4];
            #pragma unroll
            for (int mt = 0; mt < 2; mt++)
                ldmx4(a[mt], cbase + a_off[mt] + ks * 32);
            ldmx4(b, cbase + b_off + ks * 32);
            #pragma unroll
            for (int mt = 0; mt < 2; mt++)
                #pragma unroll
                for (int nt = 0; nt < 2; nt++)
                    mma_fp16(acc[mt][nt], a[mt], &b[nt * 2]);
        }
    }

    float* a4f = reinterpret_cast<float*>(g_a4);
    float* b4f = reinterpret_cast<float*>(g_b4);
    #pragma unroll
    for (int mt = 0; mt < 2; mt++) {
        int rg = m0 + wm * 32 + mt * 16 + (lane >> 2);
        #pragma unroll
        for (int nt = 0; nt < 2; nt++) {
            int col = wn * 16 + nt * 8 + (lane & 3) * 2;
            #pragma unroll
            for (int half = 0; half < 2; half++) {
                int row = rg + half * 8;
                float v0 = acc[mt][nt][half * 2 + 0];
                float v1 = acc[mt][nt][half * 2 + 1];
                if (col < 32) {
                    atom_out[row * FF + col]     = v0 + b_atom[col];
                    atom_out[row * FF + col + 1] = v1 + b_atom[col + 1];
                } else if (col < 36) {
                    a4f[row * 4 + (col - 32)]     = v0;
                    a4f[row * 4 + (col - 32) + 1] = v1;
                } else if (col < 40) {
                    b4f[row * 4 + (col - 36)]     = v0;
                    b4f[row * 4 + (col - 36) + 1] = v1;
                }
            }
        }
    }
}

// ---------------- bond logits: 4 coalesced float4 per thread (R11 proven) ----
__global__ void __launch_bounds__(256) bond_kernel(const float* __restrict__ b_bond,
                                                   float4* __restrict__ bond) {
    int i = blockIdx.y;
    int jbase = blockIdx.x * 1024 + threadIdx.x;
    float4 bb = make_float4(__ldg(&b_bond[0]), __ldg(&b_bond[1]),
                            __ldg(&b_bond[2]), __ldg(&b_bond[3]));
    float4 ai = g_a4[i];
    float4 bi = g_b4[i];
    float4 w[4];
    #pragma unroll
    for (int k = 0; k < 4; k++) {
        int j = jbase + k * 256;
        float4 r = make_float4(0.f, 0.f, 0.f, 0.f);
        if (i != j) {
            float4 av = (j < i) ? g_a4[j] : ai;
            float4 bv = (j < i) ? bi : g_b4[j];
            r.x = av.x + bv.x + bb.x;
            r.y = av.y + bv.y + bb.y;
            r.z = av.z + bv.z + bb.z;
            r.w = av.w + bv.w + bb.w;
        }
        w[k] = r;
    }
    #pragma unroll
    for (int k = 0; k < 4; k++)
        __stcs(&bond[(size_t)i * NN + jbase + k * 256], w[k]);
}

// ---------------- launch ----------------------------------------------------
extern "C" void kernel_launch(void* const* d_in, const int* in_sizes, int n_in,
                              void* d_out, int out_size) {
    const float* x        = (const float*)d_in[0];
    const float* adj      = (const float*)d_in[1];
    const float* w_self1  = (const float*)d_in[2];
    const float* b_self1  = (const float*)d_in[3];
    const float* w_neigh1 = (const float*)d_in[4];
    const float* b_neigh1 = (const float*)d_in[5];
    const float* w_self2  = (const float*)d_in[6];
    const float* b_self2  = (const float*)d_in[7];
    const float* w_neigh2 = (const float*)d_in[8];
    const float* b_neigh2 = (const float*)d_in[9];
    const float* w_atom   = (const float*)d_in[10];
    const float* b_atom   = (const float*)d_in[11];
    const float* w_bond   = (const float*)d_in[12];
    const float* b_bond   = (const float*)d_in[13];
    float* out = (float*)d_out;

    float *p_agg1p, *p_h2p;
    __nv_bfloat16 *p_adjb, *p_h1T, *p_xTb;
    __half *p_h1h, *p_agg2h, *p_h2h, *p_ws2h, *p_wn2h, *p_w48h;
    cudaGetSymbolAddress((void**)&p_agg1p, g_agg1p);
    cudaGetSymbolAddress((void**)&p_h2p,   g_h2p);
    cudaGetSymbolAddress((void**)&p_adjb,  g_adjb);
    cudaGetSymbolAddress((void**)&p_h1T,   g_h1T);
    cudaGetSymbolAddress((void**)&p_xTb,   g_xTb);
    cudaGetSymbolAddress((void**)&p_h1h,   g_h1h);
    cudaGetSymbolAddress((void**)&p_agg2h, g_agg2h);
    cudaGetSymbolAddress((void**)&p_h2h,   g_h2h);
    cudaGetSymbolAddress((void**)&p_ws2h,  g_ws2h);
    cudaGetSymbolAddress((void**)&p_wn2h,  g_wn2h);
    cudaGetSymbolAddress((void**)&p_w48h,  g_w48h);

    cudaFuncSetAttribute(mma_agg1_kernel,
                         cudaFuncAttributeMaxDynamicSharedMemorySize, A1_SMEM_TOTAL);
    cudaFuncSetAttribute(mma_agg2_kernel,
                         cudaFuncAttributeMaxDynamicSharedMemorySize, A2_SMEM_TOTAL);
    cudaFuncSetAttribute(mma_gc2a_kernel,
                         cudaFuncAttributeMaxDynamicSharedMemorySize, MMA_SMEM_TOTAL);
    cudaFuncSetAttribute(mma_gc2b_kernel,
                         cudaFuncAttributeMaxDynamicSharedMemorySize, MMA_SMEM_TOTAL);
    cudaFuncSetAttribute(head_mma_kernel,
                         cudaFuncAttributeMaxDynamicSharedMemorySize, HD_SMEM_TOTAL);

    // static side stream + fork/join events (host objects, created once,
    // outside graph capture — first call is the non-captured correctness run)
    static cudaStream_t s2 = nullptr;
    static cudaEvent_t evFork = nullptr, evJoin = nullptr;
    if (s2 == nullptr) {
        cudaStreamCreateWithFlags(&s2, cudaStreamNonBlocking);
        cudaEventCreateWithFlags(&evFork, cudaEventDisableTiming);
        cudaEventCreateWithFlags(&evJoin, cudaEventDisableTiming);
    }

    // 1. mega-prep
    megaprep_kernel<<<NN + 1152, 256>>>(adj, p_adjb, w_self2, w_neigh2,
                                        x, w_atom, w_bond);
    // 2. agg1 partials (K-split x16)
    mma_agg1_kernel<<<dim3(KSPLIT, NN / 128), 256, A1_SMEM_TOTAL>>>(
        p_adjb, p_xTb, p_agg1p);
    // 3. h1 layer
    fused_gc1_kernel<<<dim3(HH / 128, NN / 128), 256>>>(
        x, w_self1, b_self1, p_agg1p, w_neigh1, b_neigh1, p_h1T, p_h1h);

    // fork: gc2a (self-GEMM) runs concurrently with agg2
    cudaEventRecord(evFork, 0);
    cudaStreamWaitEvent(s2, evFork, 0);
    mma_gc2a_kernel<<<dim3(HH / 128, NN / 128), 256, MMA_SMEM_TOTAL, s2>>>(
        p_h1h, p_ws2h, p_h2p);
    // 4. agg2 on main stream
    mma_agg2_kernel<<<dim3(HH / 128, NN / 64), 256, A2_SMEM_TOTAL>>>(
        p_adjb, p_h1T, p_agg2h);
    // join
    cudaEventRecord(evJoin, s2);
    cudaStreamWaitEvent(0, evJoin, 0);

    // 5. gc2b: h2 = relu(P + agg2@Wn2^T + b)
    mma_gc2b_kernel<<<dim3(HH / 128, NN / 128), 256, MMA_SMEM_TOTAL>>>(
        p_agg2h, p_wn2h, p_h2p, b_self2, b_neigh2, p_h2h);
    // 6. head via HMMA
    head_mma_kernel<<<dim3(1, NN / 64), 256, HD_SMEM_TOTAL>>>(
        p_h2h, p_w48h, b_atom, out);
    // 7. bond logits
    bond_kernel<<<dim3(NN / 1024, NN), 256>>>(b_bond, (float4*)(out + (size_t)NN * FF));
}

// round 15
// speedup vs baseline: 1.0567x; 1.0567x over previous
#include <cuda_runtime.h>
#include <cuda_bf16.h>
#include <cuda_fp16.h>
#include <cstdint>

#define NN 4096
#define HH 512
#define FF 32
#define KSPLIT 16

// ---------------- scratch (device globals: no allocation allowed) ----------
__device__ float  g_deg[NN];
__device__ float  g_agg1p[KSPLIT * NN * FF];        // K-split partials (8 MB)
__device__ __half g_h2ph[(size_t)NN * HH];          // gc2 self-partial fp16 (4 MB)
__device__ float4 g_a4[NN];
__device__ float4 g_b4[NN];
__device__ __nv_bfloat16 g_adjb[(size_t)NN * NN];   // adj bf16 (32 MB)
__device__ __nv_bfloat16 g_h1T[(size_t)HH * NN];    // h1^T bf16 (4 MB)
__device__ __half        g_h1h[(size_t)NN * HH];    // h1 fp16 row-major (4 MB)
__device__ __half        g_agg2h[(size_t)NN * HH];  // agg2 fp16 row-major (4 MB)
__device__ __half        g_h2h[(size_t)NN * HH];    // h2 fp16 row-major (4 MB)
__device__ __nv_bfloat16 g_xTb[(size_t)FF * NN];    // x^T bf16 (0.25 MB)
__device__ __half        g_ws2h[(size_t)HH * HH];   // w_self2 fp16
__device__ __half        g_wn2h[(size_t)HH * HH];   // w_neigh2 fp16
__device__ __half        g_w48h[(size_t)64 * HH];   // head weights fp16

// ---------------- mega-prep: deg + adj->bf16 (vectorized) + conversions -----
__global__ void __launch_bounds__(256) megaprep_kernel(
    const float* __restrict__ adj, __nv_bfloat16* __restrict__ adjb,
    const float* __restrict__ ws2, const float* __restrict__ wn2,
    const float* __restrict__ x,
    const float* __restrict__ w_atom, const float* __restrict__ w_bond) {
    int b = blockIdx.x;
    int tid = threadIdx.x;
    if (b < NN) {
        const float4* row = reinterpret_cast<const float4*>(adj + (size_t)b * NN);
        uint4* brow = reinterpret_cast<uint4*>(adjb + (size_t)b * NN);
        float s = 0.f;
        for (int t = tid; t < NN / 8; t += 256) {
            float4 v0 = row[t * 2];
            float4 v1 = row[t * 2 + 1];
            s += (v0.x + v0.y) + (v0.z + v0.w) + (v1.x + v1.y) + (v1.z + v1.w);
            __nv_bfloat162 p0 = __floats2bfloat162_rn(v0.x, v0.y);
            __nv_bfloat162 p1 = __floats2bfloat162_rn(v0.z, v0.w);
            __nv_bfloat162 p2 = __floats2bfloat162_rn(v1.x, v1.y);
            __nv_bfloat162 p3 = __floats2bfloat162_rn(v1.z, v1.w);
            uint4 pk;
            pk.x = *reinterpret_cast<uint32_t*>(&p0);
            pk.y = *reinterpret_cast<uint32_t*>(&p1);
            pk.z = *reinterpret_cast<uint32_t*>(&p2);
            pk.w = *reinterpret_cast<uint32_t*>(&p3);
            brow[t] = pk;
        }
        #pragma unroll
        for (int off = 16; off > 0; off >>= 1)
            s += __shfl_down_sync(0xffffffffu, s, off);
        __shared__ float red[8];
        if ((tid & 31) == 0) red[tid >> 5] = s;
        __syncthreads();
        if (tid == 0) {
            float t = red[0] + red[1] + red[2] + red[3]
                    + red[4] + red[5] + red[6] + red[7];
            g_deg[b] = fmaxf(t, 1.0f);
        }
    } else if (b < NN + 512) {
        int i = (b - NN) * 256 + tid;
        float2 a = reinterpret_cast<const float2*>(ws2)[i];
        float2 c = reinterpret_cast<const float2*>(wn2)[i];
        reinterpret_cast<__half2*>(g_ws2h)[i] = __floats2half2_rn(a.x, a.y);
        reinterpret_cast<__half2*>(g_wn2h)[i] = __floats2half2_rn(c.x, c.y);
    } else if (b < NN + 1024) {
        int i = (b - NN - 512) * 256 + tid;
        int r = i >> 5, c = i & 31;
        g_xTb[(size_t)c * NN + r] = __float2bfloat16(x[i]);
    } else {
        int i = (b - NN - 1024) * 256 + tid;
        int r = i >> 9, k = i & 511;
        float v;
        if (r < 32)      v = w_atom[r * HH + k];
        else if (r < 36) v = w_bond[(r - 32) * (2 * HH) + k];
        else if (r < 40) v = w_bond[(r - 36) * (2 * HH) + HH + k];
        else             v = 0.f;
        g_w48h[(size_t)r * HH + k] = __float2half(v);
    }
}

// ================= common HMMA helpers =======================================
#define ROWB 72
#define TILE_BYTES (128 * ROWB * 2)
#define BUF_BYTES  (2 * TILE_BYTES)
#define MMA_SMEM_TOTAL (2 * BUF_BYTES)

__device__ __forceinline__ uint32_t smem_u32(const void* p) {
    uint32_t a;
    asm("{ .reg .u64 t; cvta.to.shared.u64 t, %1; cvt.u32.u64 %0, t; }"
        : "=r"(a) : "l"(p));
    return a;
}
__device__ __forceinline__ void cp16(uint32_t saddr, const void* gaddr) {
    asm volatile("cp.async.cg.shared.global [%0], [%1], 16;"
                 :: "r"(saddr), "l"(gaddr));
}
__device__ __forceinline__ void ldmx4(uint32_t* r, uint32_t addr) {
    asm volatile("ldmatrix.sync.aligned.m8n8.x4.shared.b16 {%0,%1,%2,%3}, [%4];"
                 : "=r"(r[0]), "=r"(r[1]), "=r"(r[2]), "=r"(r[3]) : "r"(addr));
}
__device__ __forceinline__ void mma_bf16(float* c, const uint32_t* a, const uint32_t* b) {
    asm volatile(
        "mma.sync.aligned.m16n8k16.row.col.f32.bf16.bf16.f32 "
        "{%0,%1,%2,%3}, {%4,%5,%6,%7}, {%8,%9}, {%0,%1,%2,%3};"
        : "+f"(c[0]), "+f"(c[1]), "+f"(c[2]), "+f"(c[3])
        : "r"(a[0]), "r"(a[1]), "r"(a[2]), "r"(a[3]), "r"(b[0]), "r"(b[1]));
}
__device__ __forceinline__ void mma_fp16(float* c, const uint32_t* a, const uint32_t* b) {
    asm volatile(
        "mma.sync.aligned.m16n8k16.row.col.f32.f16.f16.f32 "
        "{%0,%1,%2,%3}, {%4,%5,%6,%7}, {%8,%9}, {%0,%1,%2,%3};"
        : "+f"(c[0]), "+f"(c[1]), "+f"(c[2]), "+f"(c[3])
        : "r"(a[0]), "r"(a[1]), "r"(a[2]), "r"(a[3]), "r"(b[0]), "r"(b[1]));
}

template <typename T>
__device__ __forceinline__ void stage_tile(uint32_t dst, const T* __restrict__ src,
                                           int row0, int k0, size_t stride, int tid,
                                           int nrows) {
    int per = (nrows * 8) / 256;
    for (int q = 0; q < per; q++) {
        int idx = tid + q * 256;
        int r = idx >> 3, c = idx & 7;
        uint32_t soff = (uint32_t)(r * ROWB + c * 8) * 2;
        cp16(dst + soff, src + (size_t)(row0 + r) * stride + k0 + c * 8);
    }
}

// ---------------- gc1: h1 = relu(x Ws1^T + agg1 Wn1^T + b), K=32 ------------
__global__ void __launch_bounds__(256) fused_gc1_kernel(
    const float* __restrict__ A1, const float* __restrict__ W1, const float* __restrict__ b1,
    const float* __restrict__ P, const float* __restrict__ W2, const float* __restrict__ b2,
    __nv_bfloat16* __restrict__ CT, __half* __restrict__ CH) {
    const int K = FF;
    __shared__ float As1[2][8][128], As2[2][8][128];
    __shared__ float Bs1[2][8][128], Bs2[2][8][128];

    int tid = threadIdx.x, bx = blockIdx.x, by = blockIdx.y;
    int tx = tid & 15, ty = tid >> 4;
    int lRow = tid >> 1, lC = (tid & 1) * 4;

    const float* A1p = A1 + (size_t)(by * 128 + lRow) * K + lC;
    const float* W1p = W1 + (size_t)(bx * 128 + lRow) * K + lC;
    const float* W2p = W2 + (size_t)(bx * 128 + lRow) * K + lC;

    int a2row = by * 128 + lRow;
    size_t a2idx = (size_t)a2row * FF + lC;
    float dinv = 1.0f / g_deg[a2row];

    auto loadA2 = [&](int k) -> float4 {
        float4 s = make_float4(0.f, 0.f, 0.f, 0.f);
        #pragma unroll
        for (int p = 0; p < KSPLIT; p++) {
            float4 v = *(const float4*)(P + (size_t)p * NN * FF + a2idx + k);
            s.x += v.x; s.y += v.y; s.z += v.z; s.w += v.w;
        }
        s.x *= dinv; s.y *= dinv; s.z *= dinv; s.w *= dinv;
        return s;
    };

    float acc[8][8] = {};

    {
        float4 a1 = *(const float4*)A1p;
        float4 a2 = loadA2(0);
        float4 w1 = *(const float4*)W1p;
        float4 w2 = *(const float4*)W2p;
        As1[0][lC + 0][lRow] = a1.x; As1[0][lC + 1][lRow] = a1.y;
        As1[0][lC + 2][lRow] = a1.z; As1[0][lC + 3][lRow] = a1.w;
        As2[0][lC + 0][lRow] = a2.x; As2[0][lC + 1][lRow] = a2.y;
        As2[0][lC + 2][lRow] = a2.z; As2[0][lC + 3][lRow] = a2.w;
        Bs1[0][lC + 0][lRow] = w1.x; Bs1[0][lC + 1][lRow] = w1.y;
        Bs1[0][lC + 2][lRow] = w1.z; Bs1[0][lC + 3][lRow] = w1.w;
        Bs2[0][lC + 0][lRow] = w2.x; Bs2[0][lC + 1][lRow] = w2.y;
        Bs2[0][lC + 2][lRow] = w2.z; Bs2[0][lC + 3][lRow] = w2.w;
    }
    __syncthreads();

    int nIter = K / 8;
    for (int it = 0; it < nIter; ++it) {
        int cur = it & 1;
        float4 na1, na2, nw1, nw2;
        bool more = (it + 1 < nIter);
        if (more) {
            int k = (it + 1) * 8;
            na1 = *(const float4*)(A1p + k);
            na2 = loadA2(k);
            nw1 = *(const float4*)(W1p + k);
            nw2 = *(const float4*)(W2p + k);
        }
        #pragma unroll
        for (int k = 0; k < 8; k++) {
            float ar1[8], ar2[8], wr1[8], wr2[8];
            #pragma unroll
            for (int i = 0; i < 8; i++) { ar1[i] = As1[cur][k][ty * 8 + i]; ar2[i] = As2[cur][k][ty * 8 + i]; }
            #pragma unroll
            for (int j = 0; j < 8; j++) { wr1[j] = Bs1[cur][k][tx * 8 + j]; wr2[j] = Bs2[cur][k][tx * 8 + j]; }
            #pragma unroll
            for (int i = 0; i < 8; i++)
                #pragma unroll
                for (int j = 0; j < 8; j++)
                    acc[i][j] += ar1[i] * wr1[j] + ar2[i] * wr2[j];
        }
        if (more) {
            int nxt = cur ^ 1;
            __syncthreads();
            As1[nxt][lC + 0][lRow] = na1.x; As1[nxt][lC + 1][lRow] = na1.y;
            As1[nxt][lC + 2][lRow] = na1.z; As1[nxt][lC + 3][lRow] = na1.w;
            As2[nxt][lC + 0][lRow] = na2.x; As2[nxt][lC + 1][lRow] = na2.y;
            As2[nxt][lC + 2][lRow] = na2.z; As2[nxt][lC + 3][lRow] = na2.w;
            Bs1[nxt][lC + 0][lRow] = nw1.x; Bs1[nxt][lC + 1][lRow] = nw1.y;
            Bs1[nxt][lC + 2][lRow] = nw1.z; Bs1[nxt][lC + 3][lRow] = nw1.w;
            Bs2[nxt][lC + 0][lRow] = nw2.x; Bs2[nxt][lC + 1][lRow] = nw2.y;
            Bs2[nxt][lC + 2][lRow] = nw2.z; Bs2[nxt][lC + 3][lRow] = nw2.w;
            __syncthreads();
        }
    }

    int row0 = by * 128 + ty * 8;
    int col0 = bx * 128 + tx * 8;
    float bias[8];
    #pragma unroll
    for (int j = 0; j < 8; j++) bias[j] = b1[col0 + j] + b2[col0 + j];
    #pragma unroll
    for (int i = 0; i < 8; i++)
        #pragma unroll
        for (int j = 0; j < 8; j++)
            acc[i][j] = fmaxf(acc[i][j] + bias[j], 0.f);

    #pragma unroll
    for (int i = 0; i < 8; i++) {
        __half hv[8];
        #pragma unroll
        for (int j = 0; j < 8; j++) hv[j] = __float2half(acc[i][j]);
        *(uint4*)&CH[(size_t)(row0 + i) * HH + col0] = *(uint4*)hv;
    }
    #pragma unroll
    for (int j = 0; j < 8; j++) {
        __nv_bfloat16 tv[8];
        #pragma unroll
        for (int i = 0; i < 8; i++) tv[i] = __float2bfloat16(acc[i][j]);
        *(uint4*)&CT[(size_t)(col0 + j) * NN + row0] = *(uint4*)tv;
    }
}

// ================= agg1 partials: K-split x16, single-sync pipeline =========
#define A1_B_TILE (32 * ROWB * 2)
#define A1_BUF (TILE_BYTES + A1_B_TILE)
#define A1_SMEM_TOTAL (2 * A1_BUF)

__global__ void __launch_bounds__(256) mma_agg1_kernel(
    const __nv_bfloat16* __restrict__ Ab, const __nv_bfloat16* __restrict__ Bb,
    float* __restrict__ Pout) {
    extern __shared__ char smem[];
    uint32_t sbase = smem_u32(smem);
    const int tid = threadIdx.x, lane = tid & 31, wm = tid >> 5;
    const int m0 = blockIdx.y * 128;
    const int kbase = blockIdx.x * (NN / KSPLIT);
    float* out = Pout + (size_t)blockIdx.x * NN * FF;

    const int sel = lane >> 3, lr = lane & 7;
    uint32_t a_off = (uint32_t)(((wm * 16 + (sel & 1) * 8 + lr) * ROWB
                                 + (sel >> 1) * 8) * 2);
    uint32_t b_off[2];
    #pragma unroll
    for (int ntp = 0; ntp < 2; ntp++)
        b_off[ntp] = (uint32_t)(TILE_BYTES
                     + ((ntp * 16 + (sel >> 1) * 8 + lr) * ROWB + (sel & 1) * 8) * 2);

    float acc[4][4] = {};

    const int NCHUNK = (NN / KSPLIT) / 64;
    stage_tile(sbase, Ab, m0, kbase, NN, tid, 128);
    stage_tile(sbase + TILE_BYTES, Bb, 0, kbase, NN, tid, 32);
    asm volatile("cp.async.commit_group;" ::: "memory");

    for (int it = 0; it < NCHUNK; ++it) {
        asm volatile("cp.async.wait_group 0;" ::: "memory");
        __syncthreads();
        if (it + 1 < NCHUNK) {
            uint32_t nb = sbase + ((it + 1) & 1) * A1_BUF;
            stage_tile(nb, Ab, m0, kbase + (it + 1) * 64, NN, tid, 128);
            stage_tile(nb + TILE_BYTES, Bb, 0, kbase + (it + 1) * 64, NN, tid, 32);
            asm volatile("cp.async.commit_group;" ::: "memory");
        }
        uint32_t cbase = sbase + (it & 1) * A1_BUF;
        #pragma unroll
        for (int ks = 0; ks < 4; ks++) {
            uint32_t a[4], b[2][4];
            ldmx4(a, cbase + a_off + ks * 32);
            #pragma unroll
            for (int ntp = 0; ntp < 2; ntp++)
                ldmx4(b[ntp], cbase + b_off[ntp] + ks * 32);
            #pragma unroll
            for (int nt = 0; nt < 4; nt++)
                mma_bf16(acc[nt], a, &b[nt >> 1][(nt & 1) * 2]);
        }
    }

    int rg = m0 + wm * 16 + (lane >> 2);
    #pragma unroll
    for (int nt = 0; nt < 4; nt++) {
        int col = nt * 8 + (lane & 3) * 2;
        *(float2*)&out[(size_t)rg * FF + col] = make_float2(acc[nt][0], acc[nt][1]);
        *(float2*)&out[(size_t)(rg + 8) * FF + col] = make_float2(acc[nt][2], acc[nt][3]);
    }
}

// ================= agg2: 64x128 tile, 3-stage, single-sync (R11 proven) =====
#define A2_A_TILE (64 * ROWB * 2)
#define A2_BUF (A2_A_TILE + TILE_BYTES)
#define A2_SMEM_TOTAL (3 * A2_BUF)

__global__ void __launch_bounds__(256) mma_agg2_kernel(
    const __nv_bfloat16* __restrict__ Ab,
    const __nv_bfloat16* __restrict__ Bb,
    __half* __restrict__ Cout) {
    extern __shared__ char smem[];
    uint32_t sbase = smem_u32(smem);

    const int tid = threadIdx.x;
    const int lane = tid & 31, wid = tid >> 5;
    const int wm = wid & 1, wn = wid >> 1;
    const int m0 = blockIdx.y * 64, n0 = blockIdx.x * 128;

    const int sel = lane >> 3, lr = lane & 7;
    uint32_t a_off[2], b_off[2];
    #pragma unroll
    for (int mt = 0; mt < 2; mt++)
        a_off[mt] = (uint32_t)(((wm * 32 + mt * 16 + (sel & 1) * 8 + lr) * ROWB
                                + (sel >> 1) * 8) * 2);
    #pragma unroll
    for (int ntp = 0; ntp < 2; ntp++)
        b_off[ntp] = (uint32_t)(A2_A_TILE
                     + ((wn * 32 + ntp * 16 + (sel >> 1) * 8 + lr) * ROWB
                        + (sel & 1) * 8) * 2);

    float acc[2][4][4] = {};

    const int NCHUNK = NN / 64;
    #pragma unroll
    for (int s = 0; s < 2; s++) {
        uint32_t sb = sbase + s * A2_BUF;
        stage_tile(sb, Ab, m0, s * 64, NN, tid, 64);
        stage_tile(sb + A2_A_TILE, Bb, n0, s * 64, NN, tid, 128);
        asm volatile("cp.async.commit_group;" ::: "memory");
    }

    int slot = 0;
    for (int it = 0; it < NCHUNK; ++it) {
        if (it + 1 < NCHUNK) {
            asm volatile("cp.async.wait_group 1;" ::: "memory");
        } else {
            asm volatile("cp.async.wait_group 0;" ::: "memory");
        }
        __syncthreads();
        if (it + 2 < NCHUNK) {
            int ns = slot + 2; if (ns >= 3) ns -= 3;
            uint32_t nb = sbase + ns * A2_BUF;
            stage_tile(nb, Ab, m0, (it + 2) * 64, NN, tid, 64);
            stage_tile(nb + A2_A_TILE, Bb, n0, (it + 2) * 64, NN, tid, 128);
            asm volatile("cp.async.commit_group;" ::: "memory");
        }

        uint32_t cbase = sbase + slot * A2_BUF;
        #pragma unroll
        for (int ks = 0; ks < 4; ks++) {
            uint32_t a[2][4], b[2][4];
            #pragma unroll
            for (int mt = 0; mt < 2; mt++)
                ldmx4(a[mt], cbase + a_off[mt] + ks * 32);
            #pragma unroll
            for (int ntp = 0; ntp < 2; ntp++)
                ldmx4(b[ntp], cbase + b_off[ntp] + ks * 32);
            #pragma unroll
            for (int mt = 0; mt < 2; mt++)
                #pragma unroll
                for (int nt = 0; nt < 4; nt++)
                    mma_bf16(acc[mt][nt], a[mt], &b[nt >> 1][(nt & 1) * 2]);
        }
        slot = slot + 1; if (slot >= 3) slot -= 3;
    }

    #pragma unroll
    for (int mt = 0; mt < 2; mt++) {
        int rg = m0 + wm * 32 + mt * 16 + (lane >> 2);
        float inv0 = 1.0f / g_deg[rg];
        float inv1 = 1.0f / g_deg[rg + 8];
        #pragma unroll
        for (int nt = 0; nt < 4; nt++) {
            int col = n0 + wn * 32 + nt * 8 + (lane & 3) * 2;
            *(__half2*)&Cout[(size_t)rg * HH + col] =
                __floats2half2_rn(acc[mt][nt][0] * inv0, acc[mt][nt][1] * inv0);
            *(__half2*)&Cout[(size_t)(rg + 8) * HH + col] =
                __floats2half2_rn(acc[mt][nt][2] * inv1, acc[mt][nt][3] * inv1);
        }
    }
}

// ================= gc2a: P = h1h @ ws2^T (fp16 partial), K=512 ===============
__global__ void __launch_bounds__(256) mma_gc2a_kernel(
    const __half* __restrict__ A1, const __half* __restrict__ W1,
    __half* __restrict__ Pout) {
    extern __shared__ char smem[];
    uint32_t sbase = smem_u32(smem);

    const int tid = threadIdx.x;
    const int lane = tid & 31, wid = tid >> 5;
    const int wm = wid & 3, wn = wid >> 2;
    const int m0 = blockIdx.y * 128, n0 = blockIdx.x * 128;

    const int sel = lane >> 3, lr = lane & 7;
    uint32_t a_off[2], b_off[4];
    #pragma unroll
    for (int mt = 0; mt < 2; mt++)
        a_off[mt] = (uint32_t)(((wm * 32 + mt * 16 + (sel & 1) * 8 + lr) * ROWB
                                + (sel >> 1) * 8) * 2);
    #pragma unroll
    for (int ntp = 0; ntp < 4; ntp++)
        b_off[ntp] = (uint32_t)(TILE_BYTES
                     + ((wn * 64 + ntp * 16 + (sel >> 1) * 8 + lr) * ROWB
                        + (sel & 1) * 8) * 2);

    float acc[2][8][4] = {};

    const int NCHUNK = 8;
    stage_tile(sbase, A1, m0, 0, HH, tid, 128);
    stage_tile(sbase + TILE_BYTES, W1, n0, 0, HH, tid, 128);
    asm volatile("cp.async.commit_group;" ::: "memory");

    for (int it = 0; it < NCHUNK; ++it) {
        asm volatile("cp.async.wait_group 0;" ::: "memory");
        __syncthreads();
        if (it + 1 < NCHUNK) {
            int k0 = (it + 1) * 64;
            uint32_t nb = sbase + ((it + 1) & 1) * BUF_BYTES;
            stage_tile(nb, A1, m0, k0, HH, tid, 128);
            stage_tile(nb + TILE_BYTES, W1, n0, k0, HH, tid, 128);
            asm volatile("cp.async.commit_group;" ::: "memory");
        }
        uint32_t cbase = sbase + (it & 1) * BUF_BYTES;
        #pragma unroll
        for (int ks = 0; ks < 4; ks++) {
            uint32_t a[2][4], b[4][4];
            #pragma unroll
            for (int mt = 0; mt < 2; mt++)
                ldmx4(a[mt], cbase + a_off[mt] + ks * 32);
            #pragma unroll
            for (int ntp = 0; ntp < 4; ntp++)
                ldmx4(b[ntp], cbase + b_off[ntp] + ks * 32);
            #pragma unroll
            for (int mt = 0; mt < 2; mt++)
                #pragma unroll
                for (int nt = 0; nt < 8; nt++)
                    mma_fp16(acc[mt][nt], a[mt], &b[nt >> 1][(nt & 1) * 2]);
        }
    }

    #pragma unroll
    for (int mt = 0; mt < 2; mt++) {
        int rg = m0 + wm * 32 + mt * 16 + (lane >> 2);
        #pragma unroll
        for (int nt = 0; nt < 8; nt++) {
            int col = n0 + wn * 64 + nt * 8 + (lane & 3) * 2;
            *(__half2*)&Pout[(size_t)rg * HH + col] =
                __floats2half2_rn(acc[mt][nt][0], acc[mt][nt][1]);
            *(__half2*)&Pout[(size_t)(rg + 8) * HH + col] =
                __floats2half2_rn(acc[mt][nt][2], acc[mt][nt][3]);
        }
    }
}

// ================= gc2b: h2 = relu(P + agg2h @ wn2^T + b), K=512 =============
__global__ void __launch_bounds__(256) mma_gc2b_kernel(
    const __half* __restrict__ A2, const __half* __restrict__ W2,
    const __half* __restrict__ P,
    const float* __restrict__ b1, const float* __restrict__ b2,
    __half* __restrict__ Cout) {
    extern __shared__ char smem[];
    uint32_t sbase = smem_u32(smem);

    const int tid = threadIdx.x;
    const int lane = tid & 31, wid = tid >> 5;
    const int wm = wid & 3, wn = wid >> 2;
    const int m0 = blockIdx.y * 128, n0 = blockIdx.x * 128;

    const int sel = lane >> 3, lr = lane & 7;
    uint32_t a_off[2], b_off[4];
    #pragma unroll
    for (int mt = 0; mt < 2; mt++)
        a_off[mt] = (uint32_t)(((wm * 32 + mt * 16 + (sel & 1) * 8 + lr) * ROWB
                                + (sel >> 1) * 8) * 2);
    #pragma unroll
    for (int ntp = 0; ntp < 4; ntp++)
        b_off[ntp] = (uint32_t)(TILE_BYTES
                     + ((wn * 64 + ntp * 16 + (sel >> 1) * 8 + lr) * ROWB
                        + (sel & 1) * 8) * 2);

    float acc[2][8][4] = {};

    const int NCHUNK = 8;
    stage_tile(sbase, A2, m0, 0, HH, tid, 128);
    stage_tile(sbase + TILE_BYTES, W2, n0, 0, HH, tid, 128);
    asm volatile("cp.async.commit_group;" ::: "memory");

    for (int it = 0; it < NCHUNK; ++it) {
        asm volatile("cp.async.wait_group 0;" ::: "memory");
        __syncthreads();
        if (it + 1 < NCHUNK) {
            int k0 = (it + 1) * 64;
            uint32_t nb = sbase + ((it + 1) & 1) * BUF_BYTES;
            stage_tile(nb, A2, m0, k0, HH, tid, 128);
            stage_tile(nb + TILE_BYTES, W2, n0, k0, HH, tid, 128);
            asm volatile("cp.async.commit_group;" ::: "memory");
        }
        uint32_t cbase = sbase + (it & 1) * BUF_BYTES;
        #pragma unroll
        for (int ks = 0; ks < 4; ks++) {
            uint32_t a[2][4], b[4][4];
            #pragma unroll
            for (int mt = 0; mt < 2; mt++)
                ldmx4(a[mt], cbase + a_off[mt] + ks * 32);
            #pragma unroll
            for (int ntp = 0; ntp < 4; ntp++)
                ldmx4(b[ntp], cbase + b_off[ntp] + ks * 32);
            #pragma unroll
            for (int mt = 0; mt < 2; mt++)
                #pragma unroll
                for (int nt = 0; nt < 8; nt++)
                    mma_fp16(acc[mt][nt], a[mt], &b[nt >> 1][(nt & 1) * 2]);
        }
    }

    #pragma unroll
    for (int mt = 0; mt < 2; mt++) {
        int rg = m0 + wm * 32 + mt * 16 + (lane >> 2);
        #pragma unroll
        for (int nt = 0; nt < 8; nt++) {
            int col = n0 + wn * 64 + nt * 8 + (lane & 3) * 2;
            float bb0 = b1[col] + b2[col];
            float bb1 = b1[col + 1] + b2[col + 1];
            __half2 p0 = *(const __half2*)&P[(size_t)rg * HH + col];
            __half2 p1 = *(const __half2*)&P[(size_t)(rg + 8) * HH + col];
            float2 pf0 = __half22float2(p0);
            float2 pf1 = __half22float2(p1);
            *(__half2*)&Cout[(size_t)rg * HH + col] =
                __floats2half2_rn(fmaxf(acc[mt][nt][0] + pf0.x + bb0, 0.f),
                                  fmaxf(acc[mt][nt][1] + pf0.y + bb1, 0.f));
            *(__half2*)&Cout[(size_t)(rg + 8) * HH + col] =
                __floats2half2_rn(fmaxf(acc[mt][nt][2] + pf1.x + bb0, 0.f),
                                  fmaxf(acc[mt][nt][3] + pf1.y + bb1, 0.f));
        }
    }
}

// ================= head via fp16 HMMA, single-sync ===========================
#define HD_TILE (64 * ROWB * 2)
#define HD_BUF (2 * HD_TILE)
#define HD_SMEM_TOTAL (2 * HD_BUF)

__global__ void __launch_bounds__(256) head_mma_kernel(
    const __half* __restrict__ A, const __half* __restrict__ B,
    const float* __restrict__ b_atom, float* __restrict__ atom_out) {
    extern __shared__ char smem[];
    uint32_t sbase = smem_u32(smem);

    const int tid = threadIdx.x;
    const int lane = tid & 31, wid = tid >> 5;
    const int wm = wid & 1, wn = wid >> 1;
    const int m0 = blockIdx.y * 64;

    const int sel = lane >> 3, lr = lane & 7;
    uint32_t a_off[2];
    #pragma unroll
    for (int mt = 0; mt < 2; mt++)
        a_off[mt] = (uint32_t)(((wm * 32 + mt * 16 + (sel & 1) * 8 + lr) * ROWB
                                + (sel >> 1) * 8) * 2);
    uint32_t b_off = (uint32_t)(HD_TILE
                     + ((wn * 16 + (sel >> 1) * 8 + lr) * ROWB + (sel & 1) * 8) * 2);

    float acc[2][2][4] = {};

    const int NCHUNK = 8;
    stage_tile(sbase, A, m0, 0, HH, tid, 64);
    stage_tile(sbase + HD_TILE, B, 0, 0, HH, tid, 64);
    asm volatile("cp.async.commit_group;" ::: "memory");

    for (int it = 0; it < NCHUNK; ++it) {
        asm volatile("cp.async.wait_group 0;" ::: "memory");
        __syncthreads();
        if (it + 1 < NCHUNK) {
            uint32_t nb = sbase + ((it + 1) & 1) * HD_BUF;
            stage_tile(nb, A, m0, (it + 1) * 64, HH, tid, 64);
            stage_tile(nb + HD_TILE, B, 0, (it + 1) * 64, HH, tid, 64);
            asm volatile("cp.async.commit_group;" ::: "memory");
        }

        uint32_t cbase = sbase + (it & 1) * HD_BUF;
        #pragma unroll
        for (int ks = 0; ks < 4; ks++) {
            uint32_t a[2][4], b[4];
            #pragma unroll
            for (int mt = 0; mt < 2; mt++)
                ldmx4(a[mt], cbase + a_off[mt] + ks * 32);
            ldmx4(b, cbase + b_off + ks * 32);
            #pragma unroll
            for (int mt = 0; mt < 2; mt++)
                #pragma unroll
                for (int nt = 0; nt < 2; nt++)
                    mma_fp16(acc[mt][nt], a[mt], &b[nt * 2]);
        }
    }

    float* a4f = reinterpret_cast<float*>(g_a4);
    float* b4f = reinterpret_cast<float*>(g_b4);
    #pragma unroll
    for (int mt = 0; mt < 2; mt++) {
        int rg = m0 + wm * 32 + mt * 16 + (lane >> 2);
        #pragma unroll
        for (int nt = 0; nt < 2; nt++) {
            int col = wn * 16 + nt * 8 + (lane & 3) * 2;
            #pragma unroll
            for (int half = 0; half < 2; half++) {
                int row = rg + half * 8;
                float v0 = acc[mt][nt][half * 2 + 0];
                float v1 = acc[mt][nt][half * 2 + 1];
                if (col < 32) {
                    atom_out[row * FF + col]     = v0 + b_atom[col];
                    atom_out[row * FF + col + 1] = v1 + b_atom[col + 1];
                } else if (col < 36) {
                    a4f[row * 4 + (col - 32)]     = v0;
                    a4f[row * 4 + (col - 32) + 1] = v1;
                } else if (col < 40) {
                    b4f[row * 4 + (col - 36)]     = v0;
                    b4f[row * 4 + (col - 36) + 1] = v1;
                }
            }
        }
    }
}

// ---------------- bond logits: 4 coalesced float4 per thread (R11 proven) ----
__global__ void __launch_bounds__(256) bond_kernel(const float* __restrict__ b_bond,
                                                   float4* __restrict__ bond) {
    int i = blockIdx.y;
    int jbase = blockIdx.x * 1024 + threadIdx.x;
    float4 bb = make_float4(__ldg(&b_bond[0]), __ldg(&b_bond[1]),
                            __ldg(&b_bond[2]), __ldg(&b_bond[3]));
    float4 ai = g_a4[i];
    float4 bi = g_b4[i];
    float4 w[4];
    #pragma unroll
    for (int k = 0; k < 4; k++) {
        int j = jbase + k * 256;
        float4 r = make_float4(0.f, 0.f, 0.f, 0.f);
        if (i != j) {
            float4 av = (j < i) ? g_a4[j] : ai;
            float4 bv = (j < i) ? bi : g_b4[j];
            r.x = av.x + bv.x + bb.x;
            r.y = av.y + bv.y + bb.y;
            r.z = av.z + bv.z + bb.z;
            r.w = av.w + bv.w + bb.w;
        }
        w[k] = r;
    }
    #pragma unroll
    for (int k = 0; k < 4; k++)
        __stcs(&bond[(size_t)i * NN + jbase + k * 256], w[k]);
}

// ---------------- launch ----------------------------------------------------
extern "C" void kernel_launch(void* const* d_in, const int* in_sizes, int n_in,
                              void* d_out, int out_size) {
    const float* x        = (const float*)d_in[0];
    const float* adj      = (const float*)d_in[1];
    const float* w_self1  = (const float*)d_in[2];
    const float* b_self1  = (const float*)d_in[3];
    const float* w_neigh1 = (const float*)d_in[4];
    const float* b_neigh1 = (const float*)d_in[5];
    const float* w_self2  = (const float*)d_in[6];
    const float* b_self2  = (const float*)d_in[7];
    const float* w_neigh2 = (const float*)d_in[8];
    const float* b_neigh2 = (const float*)d_in[9];
    const float* w_atom   = (const float*)d_in[10];
    const float* b_atom   = (const float*)d_in[11];
    const float* w_bond   = (const float*)d_in[12];
    const float* b_bond   = (const float*)d_in[13];
    float* out = (float*)d_out;

    float* p_agg1p;
    __half* p_h2ph;
    __nv_bfloat16 *p_adjb, *p_h1T, *p_xTb;
    __half *p_h1h, *p_agg2h, *p_h2h, *p_ws2h, *p_wn2h, *p_w48h;
    cudaGetSymbolAddress((void**)&p_agg1p, g_agg1p);
    cudaGetSymbolAddress((void**)&p_h2ph,  g_h2ph);
    cudaGetSymbolAddress((void**)&p_adjb,  g_adjb);
    cudaGetSymbolAddress((void**)&p_h1T,   g_h1T);
    cudaGetSymbolAddress((void**)&p_xTb,   g_xTb);
    cudaGetSymbolAddress((void**)&p_h1h,   g_h1h);
    cudaGetSymbolAddress((void**)&p_agg2h, g_agg2h);
    cudaGetSymbolAddress((void**)&p_h2h,   g_h2h);
    cudaGetSymbolAddress((void**)&p_ws2h,  g_ws2h);
    cudaGetSymbolAddress((void**)&p_wn2h,  g_wn2h);
    cudaGetSymbolAddress((void**)&p_w48h,  g_w48h);

    cudaFuncSetAttribute(mma_agg1_kernel,
                         cudaFuncAttributeMaxDynamicSharedMemorySize, A1_SMEM_TOTAL);
    cudaFuncSetAttribute(mma_agg2_kernel,
                         cudaFuncAttributeMaxDynamicSharedMemorySize, A2_SMEM_TOTAL);
    cudaFuncSetAttribute(mma_gc2a_kernel,
                         cudaFuncAttributeMaxDynamicSharedMemorySize, MMA_SMEM_TOTAL);
    cudaFuncSetAttribute(mma_gc2b_kernel,
                         cudaFuncAttributeMaxDynamicSharedMemorySize, MMA_SMEM_TOTAL);
    cudaFuncSetAttribute(head_mma_kernel,
                         cudaFuncAttributeMaxDynamicSharedMemorySize, HD_SMEM_TOTAL);

    // static lowest-priority side stream + fork/join events
    static cudaStream_t s2 = nullptr;
    static cudaEvent_t evFork = nullptr, evJoin = nullptr;
    if (s2 == nullptr) {
        int leastPrio = 0, greatestPrio = 0;
        cudaDeviceGetStreamPriorityRange(&leastPrio, &greatestPrio);
        cudaStreamCreateWithPriority(&s2, cudaStreamNonBlocking, leastPrio);
        cudaEventCreateWithFlags(&evFork, cudaEventDisableTiming);
        cudaEventCreateWithFlags(&evJoin, cudaEventDisableTiming);
    }

    // 1. mega-prep
    megaprep_kernel<<<NN + 1152, 256>>>(adj, p_adjb, w_self2, w_neigh2,
                                        x, w_atom, w_bond);
    // 2. agg1 partials (K-split x16)
    mma_agg1_kernel<<<dim3(KSPLIT, NN / 128), 256, A1_SMEM_TOTAL>>>(
        p_adjb, p_xTb, p_agg1p);
    // 3. h1 layer
    fused_gc1_kernel<<<dim3(HH / 128, NN / 128), 256>>>(
        x, w_self1, b_self1, p_agg1p, w_neigh1, b_neigh1, p_h1T, p_h1h);

    // 4. agg2 FIRST on main stream (gets SM priority)
    cudaEventRecord(evFork, 0);
    mma_agg2_kernel<<<dim3(HH / 128, NN / 64), 256, A2_SMEM_TOTAL>>>(
        p_adjb, p_h1T, p_agg2h);
    // gc2a on lowest-priority side stream, concurrent with agg2
    cudaStreamWaitEvent(s2, evFork, 0);
    mma_gc2a_kernel<<<dim3(HH / 128, NN / 128), 256, MMA_SMEM_TOTAL, s2>>>(
        p_h1h, p_ws2h, p_h2ph);
    cudaEventRecord(evJoin, s2);
    cudaStreamWaitEvent(0, evJoin, 0);

    // 5. gc2b: h2 = relu(P + agg2@Wn2^T + b)
    mma_gc2b_kernel<<<dim3(HH / 128, NN / 128), 256, MMA_SMEM_TOTAL>>>(
        p_agg2h, p_wn2h, p_h2ph, b_self2, b_neigh2, p_h2h);
    // 6. head via HMMA
    head_mma_kernel<<<dim3(1, NN / 64), 256, HD_SMEM_TOTAL>>>(
        p_h2h, p_w48h, b_atom, out);
    // 7. bond logits
    bond_kernel<<<dim3(NN / 1024, NN), 256>>>(b_bond, (float4*)(out + (size_t)NN * FF));
}

// round 16
// speedup vs baseline: 1.0606x; 1.0037x over previous
#include <cuda_runtime.h>
#include <cuda_bf16.h>
#include <cuda_fp16.h>
#include <cstdint>

#define NN 4096
#define HH 512
#define FF 32
#define KSPLIT 16

// ---------------- scratch (device globals: no allocation allowed) ----------
__device__ float  g_deg[NN];
__device__ float  g_agg1p[KSPLIT * NN * FF];        // K-split partials (8 MB)
__device__ __half g_h2ph[(size_t)NN * HH];          // gc2 self-partial fp16 (4 MB)
__device__ float4 g_a4[NN];
__device__ float4 g_b4[NN];
__device__ __nv_bfloat16 g_adjb[(size_t)NN * NN];   // adj bf16 (32 MB)
__device__ __nv_bfloat16 g_h1T[(size_t)HH * NN];    // h1^T bf16 (4 MB)
__device__ __half        g_h1h[(size_t)NN * HH];    // h1 fp16 row-major (4 MB)
__device__ __half        g_agg2h[(size_t)NN * HH];  // agg2 fp16 row-major (4 MB)
__device__ __half        g_h2h[(size_t)NN * HH];    // h2 fp16 row-major (4 MB)
__device__ __nv_bfloat16 g_xTb[(size_t)FF * NN];    // x^T bf16 (0.25 MB)
__device__ __half        g_ws2h[(size_t)HH * HH];   // w_self2 fp16
__device__ __half        g_wn2h[(size_t)HH * HH];   // w_neigh2 fp16
__device__ __half        g_w48h[(size_t)64 * HH];   // head weights fp16 (40 used)

// ---------------- mega-prep: deg + adj->bf16 (vectorized) + conversions -----
__global__ void __launch_bounds__(256) megaprep_kernel(
    const float* __restrict__ adj, __nv_bfloat16* __restrict__ adjb,
    const float* __restrict__ ws2, const float* __restrict__ wn2,
    const float* __restrict__ x,
    const float* __restrict__ w_atom, const float* __restrict__ w_bond) {
    int b = blockIdx.x;
    int tid = threadIdx.x;
    if (b < NN) {
        const float4* row = reinterpret_cast<const float4*>(adj + (size_t)b * NN);
        uint4* brow = reinterpret_cast<uint4*>(adjb + (size_t)b * NN);
        float s = 0.f;
        for (int t = tid; t < NN / 8; t += 256) {
            float4 v0 = row[t * 2];
            float4 v1 = row[t * 2 + 1];
            s += (v0.x + v0.y) + (v0.z + v0.w) + (v1.x + v1.y) + (v1.z + v1.w);
            __nv_bfloat162 p0 = __floats2bfloat162_rn(v0.x, v0.y);
            __nv_bfloat162 p1 = __floats2bfloat162_rn(v0.z, v0.w);
            __nv_bfloat162 p2 = __floats2bfloat162_rn(v1.x, v1.y);
            __nv_bfloat162 p3 = __floats2bfloat162_rn(v1.z, v1.w);
            uint4 pk;
            pk.x = *reinterpret_cast<uint32_t*>(&p0);
            pk.y = *reinterpret_cast<uint32_t*>(&p1);
            pk.z = *reinterpret_cast<uint32_t*>(&p2);
            pk.w = *reinterpret_cast<uint32_t*>(&p3);
            brow[t] = pk;
        }
        #pragma unroll
        for (int off = 16; off > 0; off >>= 1)
            s += __shfl_down_sync(0xffffffffu, s, off);
        __shared__ float red[8];
        if ((tid & 31) == 0) red[tid >> 5] = s;
        __syncthreads();
        if (tid == 0) {
            float t = red[0] + red[1] + red[2] + red[3]
                    + red[4] + red[5] + red[6] + red[7];
            g_deg[b] = fmaxf(t, 1.0f);
        }
    } else if (b < NN + 512) {
        int i = (b - NN) * 256 + tid;
        float2 a = reinterpret_cast<const float2*>(ws2)[i];
        float2 c = reinterpret_cast<const float2*>(wn2)[i];
        reinterpret_cast<__half2*>(g_ws2h)[i] = __floats2half2_rn(a.x, a.y);
        reinterpret_cast<__half2*>(g_wn2h)[i] = __floats2half2_rn(c.x, c.y);
    } else if (b < NN + 1024) {
        int i = (b - NN - 512) * 256 + tid;
        int r = i >> 5, c = i & 31;
        g_xTb[(size_t)c * NN + r] = __float2bfloat16(x[i]);
    } else {
        int i = (b - NN - 1024) * 256 + tid;
        int r = i >> 9, k = i & 511;
        float v;
        if (r < 32)      v = w_atom[r * HH + k];
        else if (r < 36) v = w_bond[(r - 32) * (2 * HH) + k];
        else if (r < 40) v = w_bond[(r - 36) * (2 * HH) + HH + k];
        else             v = 0.f;
        g_w48h[(size_t)r * HH + k] = __float2half(v);
    }
}

// ================= common HMMA helpers =======================================
#define ROWB 72
#define TILE_BYTES (128 * ROWB * 2)
#define BUF_BYTES  (2 * TILE_BYTES)
#define MMA_SMEM_TOTAL (2 * BUF_BYTES)

__device__ __forceinline__ uint32_t smem_u32(const void* p) {
    uint32_t a;
    asm("{ .reg .u64 t; cvta.to.shared.u64 t, %1; cvt.u32.u64 %0, t; }"
        : "=r"(a) : "l"(p));
    return a;
}
__device__ __forceinline__ void cp16(uint32_t saddr, const void* gaddr) {
    asm volatile("cp.async.cg.shared.global [%0], [%1], 16;"
                 :: "r"(saddr), "l"(gaddr));
}
__device__ __forceinline__ void ldmx4(uint32_t* r, uint32_t addr) {
    asm volatile("ldmatrix.sync.aligned.m8n8.x4.shared.b16 {%0,%1,%2,%3}, [%4];"
                 : "=r"(r[0]), "=r"(r[1]), "=r"(r[2]), "=r"(r[3]) : "r"(addr));
}
__device__ __forceinline__ void mma_bf16(float* c, const uint32_t* a, const uint32_t* b) {
    asm volatile(
        "mma.sync.aligned.m16n8k16.row.col.f32.bf16.bf16.f32 "
        "{%0,%1,%2,%3}, {%4,%5,%6,%7}, {%8,%9}, {%0,%1,%2,%3};"
        : "+f"(c[0]), "+f"(c[1]), "+f"(c[2]), "+f"(c[3])
        : "r"(a[0]), "r"(a[1]), "r"(a[2]), "r"(a[3]), "r"(b[0]), "r"(b[1]));
}
__device__ __forceinline__ void mma_fp16(float* c, const uint32_t* a, const uint32_t* b) {
    asm volatile(
        "mma.sync.aligned.m16n8k16.row.col.f32.f16.f16.f32 "
        "{%0,%1,%2,%3}, {%4,%5,%6,%7}, {%8,%9}, {%0,%1,%2,%3};"
        : "+f"(c[0]), "+f"(c[1]), "+f"(c[2]), "+f"(c[3])
        : "r"(a[0]), "r"(a[1]), "r"(a[2]), "r"(a[3]), "r"(b[0]), "r"(b[1]));
}

template <typename T>
__device__ __forceinline__ void stage_tile(uint32_t dst, const T* __restrict__ src,
                                           int row0, int k0, size_t stride, int tid,
                                           int nrows) {
    int per = (nrows * 8) / 256;
    for (int q = 0; q < per; q++) {
        int idx = tid + q * 256;
        int r = idx >> 3, c = idx & 7;
        uint32_t soff = (uint32_t)(r * ROWB + c * 8) * 2;
        cp16(dst + soff, src + (size_t)(row0 + r) * stride + k0 + c * 8);
    }
}

// ---------------- gc1: h1 = relu(x Ws1^T + agg1 Wn1^T + b), K=32 ------------
__global__ void __launch_bounds__(256) fused_gc1_kernel(
    const float* __restrict__ A1, const float* __restrict__ W1, const float* __restrict__ b1,
    const float* __restrict__ P, const float* __restrict__ W2, const float* __restrict__ b2,
    __nv_bfloat16* __restrict__ CT, __half* __restrict__ CH) {
    const int K = FF;
    __shared__ float As1[2][8][128], As2[2][8][128];
    __shared__ float Bs1[2][8][128], Bs2[2][8][128];

    int tid = threadIdx.x, bx = blockIdx.x, by = blockIdx.y;
    int tx = tid & 15, ty = tid >> 4;
    int lRow = tid >> 1, lC = (tid & 1) * 4;

    const float* A1p = A1 + (size_t)(by * 128 + lRow) * K + lC;
    const float* W1p = W1 + (size_t)(bx * 128 + lRow) * K + lC;
    const float* W2p = W2 + (size_t)(bx * 128 + lRow) * K + lC;

    int a2row = by * 128 + lRow;
    size_t a2idx = (size_t)a2row * FF + lC;
    float dinv = 1.0f / g_deg[a2row];

    auto loadA2 = [&](int k) -> float4 {
        float4 s = make_float4(0.f, 0.f, 0.f, 0.f);
        #pragma unroll
        for (int p = 0; p < KSPLIT; p++) {
            float4 v = *(const float4*)(P + (size_t)p * NN * FF + a2idx + k);
            s.x += v.x; s.y += v.y; s.z += v.z; s.w += v.w;
        }
        s.x *= dinv; s.y *= dinv; s.z *= dinv; s.w *= dinv;
        return s;
    };

    float acc[8][8] = {};

    {
        float4 a1 = *(const float4*)A1p;
        float4 a2 = loadA2(0);
        float4 w1 = *(const float4*)W1p;
        float4 w2 = *(const float4*)W2p;
        As1[0][lC + 0][lRow] = a1.x; As1[0][lC + 1][lRow] = a1.y;
        As1[0][lC + 2][lRow] = a1.z; As1[0][lC + 3][lRow] = a1.w;
        As2[0][lC + 0][lRow] = a2.x; As2[0][lC + 1][lRow] = a2.y;
        As2[0][lC + 2][lRow] = a2.z; As2[0][lC + 3][lRow] = a2.w;
        Bs1[0][lC + 0][lRow] = w1.x; Bs1[0][lC + 1][lRow] = w1.y;
        Bs1[0][lC + 2][lRow] = w1.z; Bs1[0][lC + 3][lRow] = w1.w;
        Bs2[0][lC + 0][lRow] = w2.x; Bs2[0][lC + 1][lRow] = w2.y;
        Bs2[0][lC + 2][lRow] = w2.z; Bs2[0][lC + 3][lRow] = w2.w;
    }
    __syncthreads();

    int nIter = K / 8;
    for (int it = 0; it < nIter; ++it) {
        int cur = it & 1;
        float4 na1, na2, nw1, nw2;
        bool more = (it + 1 < nIter);
        if (more) {
            int k = (it + 1) * 8;
            na1 = *(const float4*)(A1p + k);
            na2 = loadA2(k);
            nw1 = *(const float4*)(W1p + k);
            nw2 = *(const float4*)(W2p + k);
        }
        #pragma unroll
        for (int k = 0; k < 8; k++) {
            float ar1[8], ar2[8], wr1[8], wr2[8];
            #pragma unroll
            for (int i = 0; i < 8; i++) { ar1[i] = As1[cur][k][ty * 8 + i]; ar2[i] = As2[cur][k][ty * 8 + i]; }
            #pragma unroll
            for (int j = 0; j < 8; j++) { wr1[j] = Bs1[cur][k][tx * 8 + j]; wr2[j] = Bs2[cur][k][tx * 8 + j]; }
            #pragma unroll
            for (int i = 0; i < 8; i++)
                #pragma unroll
                for (int j = 0; j < 8; j++)
                    acc[i][j] += ar1[i] * wr1[j] + ar2[i] * wr2[j];
        }
        if (more) {
            int nxt = cur ^ 1;
            __syncthreads();
            As1[nxt][lC + 0][lRow] = na1.x; As1[nxt][lC + 1][lRow] = na1.y;
            As1[nxt][lC + 2][lRow] = na1.z; As1[nxt][lC + 3][lRow] = na1.w;
            As2[nxt][lC + 0][lRow] = na2.x; As2[nxt][lC + 1][lRow] = na2.y;
            As2[nxt][lC + 2][lRow] = na2.z; As2[nxt][lC + 3][lRow] = na2.w;
            Bs1[nxt][lC + 0][lRow] = nw1.x; Bs1[nxt][lC + 1][lRow] = nw1.y;
            Bs1[nxt][lC + 2][lRow] = nw1.z; Bs1[nxt][lC + 3][lRow] = nw1.w;
            Bs2[nxt][lC + 0][lRow] = nw2.x; Bs2[nxt][lC + 1][lRow] = nw2.y;
            Bs2[nxt][lC + 2][lRow] = nw2.z; Bs2[nxt][lC + 3][lRow] = nw2.w;
            __syncthreads();
        }
    }

    int row0 = by * 128 + ty * 8;
    int col0 = bx * 128 + tx * 8;
    float bias[8];
    #pragma unroll
    for (int j = 0; j < 8; j++) bias[j] = b1[col0 + j] + b2[col0 + j];
    #pragma unroll
    for (int i = 0; i < 8; i++)
        #pragma unroll
        for (int j = 0; j < 8; j++)
            acc[i][j] = fmaxf(acc[i][j] + bias[j], 0.f);

    #pragma unroll
    for (int i = 0; i < 8; i++) {
        __half hv[8];
        #pragma unroll
        for (int j = 0; j < 8; j++) hv[j] = __float2half(acc[i][j]);
        *(uint4*)&CH[(size_t)(row0 + i) * HH + col0] = *(uint4*)hv;
    }
    #pragma unroll
    for (int j = 0; j < 8; j++) {
        __nv_bfloat16 tv[8];
        #pragma unroll
        for (int i = 0; i < 8; i++) tv[i] = __float2bfloat16(acc[i][j]);
        *(uint4*)&CT[(size_t)(col0 + j) * NN + row0] = *(uint4*)tv;
    }
}

// ================= agg1 partials: K-split x16, single-sync pipeline =========
#define A1_B_TILE (32 * ROWB * 2)
#define A1_BUF (TILE_BYTES + A1_B_TILE)
#define A1_SMEM_TOTAL (2 * A1_BUF)

__global__ void __launch_bounds__(256) mma_agg1_kernel(
    const __nv_bfloat16* __restrict__ Ab, const __nv_bfloat16* __restrict__ Bb,
    float* __restrict__ Pout) {
    extern __shared__ char smem[];
    uint32_t sbase = smem_u32(smem);
    const int tid = threadIdx.x, lane = tid & 31, wm = tid >> 5;
    const int m0 = blockIdx.y * 128;
    const int kbase = blockIdx.x * (NN / KSPLIT);
    float* out = Pout + (size_t)blockIdx.x * NN * FF;

    const int sel = lane >> 3, lr = lane & 7;
    uint32_t a_off = (uint32_t)(((wm * 16 + (sel & 1) * 8 + lr) * ROWB
                                 + (sel >> 1) * 8) * 2);
    uint32_t b_off[2];
    #pragma unroll
    for (int ntp = 0; ntp < 2; ntp++)
        b_off[ntp] = (uint32_t)(TILE_BYTES
                     + ((ntp * 16 + (sel >> 1) * 8 + lr) * ROWB + (sel & 1) * 8) * 2);

    float acc[4][4] = {};

    const int NCHUNK = (NN / KSPLIT) / 64;
    stage_tile(sbase, Ab, m0, kbase, NN, tid, 128);
    stage_tile(sbase + TILE_BYTES, Bb, 0, kbase, NN, tid, 32);
    asm volatile("cp.async.commit_group;" ::: "memory");

    for (int it = 0; it < NCHUNK; ++it) {
        asm volatile("cp.async.wait_group 0;" ::: "memory");
        __syncthreads();
        if (it + 1 < NCHUNK) {
            uint32_t nb = sbase + ((it + 1) & 1) * A1_BUF;
            stage_tile(nb, Ab, m0, kbase + (it + 1) * 64, NN, tid, 128);
            stage_tile(nb + TILE_BYTES, Bb, 0, kbase + (it + 1) * 64, NN, tid, 32);
            asm volatile("cp.async.commit_group;" ::: "memory");
        }
        uint32_t cbase = sbase + (it & 1) * A1_BUF;
        #pragma unroll
        for (int ks = 0; ks < 4; ks++) {
            uint32_t a[4], b[2][4];
            ldmx4(a, cbase + a_off + ks * 32);
            #pragma unroll
            for (int ntp = 0; ntp < 2; ntp++)
                ldmx4(b[ntp], cbase + b_off[ntp] + ks * 32);
            #pragma unroll
            for (int nt = 0; nt < 4; nt++)
                mma_bf16(acc[nt], a, &b[nt >> 1][(nt & 1) * 2]);
        }
    }

    int rg = m0 + wm * 16 + (lane >> 2);
    #pragma unroll
    for (int nt = 0; nt < 4; nt++) {
        int col = nt * 8 + (lane & 3) * 2;
        *(float2*)&out[(size_t)rg * FF + col] = make_float2(acc[nt][0], acc[nt][1]);
        *(float2*)&out[(size_t)(rg + 8) * FF + col] = make_float2(acc[nt][2], acc[nt][3]);
    }
}

// ================= agg2: 64x128 tile, 3-stage, single-sync (proven) =========
#define A2_A_TILE (64 * ROWB * 2)
#define A2_BUF (A2_A_TILE + TILE_BYTES)
#define A2_SMEM_TOTAL (3 * A2_BUF)

__global__ void __launch_bounds__(256) mma_agg2_kernel(
    const __nv_bfloat16* __restrict__ Ab,
    const __nv_bfloat16* __restrict__ Bb,
    __half* __restrict__ Cout) {
    extern __shared__ char smem[];
    uint32_t sbase = smem_u32(smem);

    const int tid = threadIdx.x;
    const int lane = tid & 31, wid = tid >> 5;
    const int wm = wid & 1, wn = wid >> 1;
    const int m0 = blockIdx.y * 64, n0 = blockIdx.x * 128;

    const int sel = lane >> 3, lr = lane & 7;
    uint32_t a_off[2], b_off[2];
    #pragma unroll
    for (int mt = 0; mt < 2; mt++)
        a_off[mt] = (uint32_t)(((wm * 32 + mt * 16 + (sel & 1) * 8 + lr) * ROWB
                                + (sel >> 1) * 8) * 2);
    #pragma unroll
    for (int ntp = 0; ntp < 2; ntp++)
        b_off[ntp] = (uint32_t)(A2_A_TILE
                     + ((wn * 32 + ntp * 16 + (sel >> 1) * 8 + lr) * ROWB
                        + (sel & 1) * 8) * 2);

    float acc[2][4][4] = {};

    const int NCHUNK = NN / 64;
    #pragma unroll
    for (int s = 0; s < 2; s++) {
        uint32_t sb = sbase + s * A2_BUF;
        stage_tile(sb, Ab, m0, s * 64, NN, tid, 64);
        stage_tile(sb + A2_A_TILE, Bb, n0, s * 64, NN, tid, 128);
        asm volatile("cp.async.commit_group;" ::: "memory");
    }

    int slot = 0;
    for (int it = 0; it < NCHUNK; ++it) {
        if (it + 1 < NCHUNK) {
            asm volatile("cp.async.wait_group 1;" ::: "memory");
        } else {
            asm volatile("cp.async.wait_group 0;" ::: "memory");
        }
        __syncthreads();
        if (it + 2 < NCHUNK) {
            int ns = slot + 2; if (ns >= 3) ns -= 3;
            uint32_t nb = sbase + ns * A2_BUF;
            stage_tile(nb, Ab, m0, (it + 2) * 64, NN, tid, 64);
            stage_tile(nb + A2_A_TILE, Bb, n0, (it + 2) * 64, NN, tid, 128);
            asm volatile("cp.async.commit_group;" ::: "memory");
        }

        uint32_t cbase = sbase + slot * A2_BUF;
        #pragma unroll
        for (int ks = 0; ks < 4; ks++) {
            uint32_t a[2][4], b[2][4];
            #pragma unroll
            for (int mt = 0; mt < 2; mt++)
                ldmx4(a[mt], cbase + a_off[mt] + ks * 32);
            #pragma unroll
            for (int ntp = 0; ntp < 2; ntp++)
                ldmx4(b[ntp], cbase + b_off[ntp] + ks * 32);
            #pragma unroll
            for (int mt = 0; mt < 2; mt++)
                #pragma unroll
                for (int nt = 0; nt < 4; nt++)
                    mma_bf16(acc[mt][nt], a[mt], &b[nt >> 1][(nt & 1) * 2]);
        }
        slot = slot + 1; if (slot >= 3) slot -= 3;
    }

    #pragma unroll
    for (int mt = 0; mt < 2; mt++) {
        int rg = m0 + wm * 32 + mt * 16 + (lane >> 2);
        float inv0 = 1.0f / g_deg[rg];
        float inv1 = 1.0f / g_deg[rg + 8];
        #pragma unroll
        for (int nt = 0; nt < 4; nt++) {
            int col = n0 + wn * 32 + nt * 8 + (lane & 3) * 2;
            *(__half2*)&Cout[(size_t)rg * HH + col] =
                __floats2half2_rn(acc[mt][nt][0] * inv0, acc[mt][nt][1] * inv0);
            *(__half2*)&Cout[(size_t)(rg + 8) * HH + col] =
                __floats2half2_rn(acc[mt][nt][2] * inv1, acc[mt][nt][3] * inv1);
        }
    }
}

// ================= gc2a: P = h1h @ ws2^T (fp16 partial), K=512 ===============
__global__ void __launch_bounds__(256) mma_gc2a_kernel(
    const __half* __restrict__ A1, const __half* __restrict__ W1,
    __half* __restrict__ Pout) {
    extern __shared__ char smem[];
    uint32_t sbase = smem_u32(smem);

    const int tid = threadIdx.x;
    const int lane = tid & 31, wid = tid >> 5;
    const int wm = wid & 3, wn = wid >> 2;
    const int m0 = blockIdx.y * 128, n0 = blockIdx.x * 128;

    const int sel = lane >> 3, lr = lane & 7;
    uint32_t a_off[2], b_off[4];
    #pragma unroll
    for (int mt = 0; mt < 2; mt++)
        a_off[mt] = (uint32_t)(((wm * 32 + mt * 16 + (sel & 1) * 8 + lr) * ROWB
                                + (sel >> 1) * 8) * 2);
    #pragma unroll
    for (int ntp = 0; ntp < 4; ntp++)
        b_off[ntp] = (uint32_t)(TILE_BYTES
                     + ((wn * 64 + ntp * 16 + (sel >> 1) * 8 + lr) * ROWB
                        + (sel & 1) * 8) * 2);

    float acc[2][8][4] = {};

    const int NCHUNK = 8;
    stage_tile(sbase, A1, m0, 0, HH, tid, 128);
    stage_tile(sbase + TILE_BYTES, W1, n0, 0, HH, tid, 128);
    asm volatile("cp.async.commit_group;" ::: "memory");

    for (int it = 0; it < NCHUNK; ++it) {
        asm volatile("cp.async.wait_group 0;" ::: "memory");
        __syncthreads();
        if (it + 1 < NCHUNK) {
            int k0 = (it + 1) * 64;
            uint32_t nb = sbase + ((it + 1) & 1) * BUF_BYTES;
            stage_tile(nb, A1, m0, k0, HH, tid, 128);
            stage_tile(nb + TILE_BYTES, W1, n0, k0, HH, tid, 128);
            asm volatile("cp.async.commit_group;" ::: "memory");
        }
        uint32_t cbase = sbase + (it & 1) * BUF_BYTES;
        #pragma unroll
        for (int ks = 0; ks < 4; ks++) {
            uint32_t a[2][4], b[4][4];
            #pragma unroll
            for (int mt = 0; mt < 2; mt++)
                ldmx4(a[mt], cbase + a_off[mt] + ks * 32);
            #pragma unroll
            for (int ntp = 0; ntp < 4; ntp++)
                ldmx4(b[ntp], cbase + b_off[ntp] + ks * 32);
            #pragma unroll
            for (int mt = 0; mt < 2; mt++)
                #pragma unroll
                for (int nt = 0; nt < 8; nt++)
                    mma_fp16(acc[mt][nt], a[mt], &b[nt >> 1][(nt & 1) * 2]);
        }
    }

    #pragma unroll
    for (int mt = 0; mt < 2; mt++) {
        int rg = m0 + wm * 32 + mt * 16 + (lane >> 2);
        #pragma unroll
        for (int nt = 0; nt < 8; nt++) {
            int col = n0 + wn * 64 + nt * 8 + (lane & 3) * 2;
            *(__half2*)&Pout[(size_t)rg * HH + col] =
                __floats2half2_rn(acc[mt][nt][0], acc[mt][nt][1]);
            *(__half2*)&Pout[(size_t)(rg + 8) * HH + col] =
                __floats2half2_rn(acc[mt][nt][2], acc[mt][nt][3]);
        }
    }
}

// ================= gc2b: h2 = relu(P + agg2h @ wn2^T + b), K=512 =============
__global__ void __launch_bounds__(256) mma_gc2b_kernel(
    const __half* __restrict__ A2, const __half* __restrict__ W2,
    const __half* __restrict__ P,
    const float* __restrict__ b1, const float* __restrict__ b2,
    __half* __restrict__ Cout) {
    extern __shared__ char smem[];
    uint32_t sbase = smem_u32(smem);

    const int tid = threadIdx.x;
    const int lane = tid & 31, wid = tid >> 5;
    const int wm = wid & 3, wn = wid >> 2;
    const int m0 = blockIdx.y * 128, n0 = blockIdx.x * 128;

    const int sel = lane >> 3, lr = lane & 7;
    uint32_t a_off[2], b_off[4];
    #pragma unroll
    for (int mt = 0; mt < 2; mt++)
        a_off[mt] = (uint32_t)(((wm * 32 + mt * 16 + (sel & 1) * 8 + lr) * ROWB
                                + (sel >> 1) * 8) * 2);
    #pragma unroll
    for (int ntp = 0; ntp < 4; ntp++)
        b_off[ntp] = (uint32_t)(TILE_BYTES
                     + ((wn * 64 + ntp * 16 + (sel >> 1) * 8 + lr) * ROWB
                        + (sel & 1) * 8) * 2);

    float acc[2][8][4] = {};

    const int NCHUNK = 8;
    stage_tile(sbase, A2, m0, 0, HH, tid, 128);
    stage_tile(sbase + TILE_BYTES, W2, n0, 0, HH, tid, 128);
    asm volatile("cp.async.commit_group;" ::: "memory");

    for (int it = 0; it < NCHUNK; ++it) {
        asm volatile("cp.async.wait_group 0;" ::: "memory");
        __syncthreads();
        if (it + 1 < NCHUNK) {
            int k0 = (it + 1) * 64;
            uint32_t nb = sbase + ((it + 1) & 1) * BUF_BYTES;
            stage_tile(nb, A2, m0, k0, HH, tid, 128);
            stage_tile(nb + TILE_BYTES, W2, n0, k0, HH, tid, 128);
            asm volatile("cp.async.commit_group;" ::: "memory");
        }
        uint32_t cbase = sbase + (it & 1) * BUF_BYTES;
        #pragma unroll
        for (int ks = 0; ks < 4; ks++) {
            uint32_t a[2][4], b[4][4];
            #pragma unroll
            for (int mt = 0; mt < 2; mt++)
                ldmx4(a[mt], cbase + a_off[mt] + ks * 32);
            #pragma unroll
            for (int ntp = 0; ntp < 4; ntp++)
                ldmx4(b[ntp], cbase + b_off[ntp] + ks * 32);
            #pragma unroll
            for (int mt = 0; mt < 2; mt++)
                #pragma unroll
                for (int nt = 0; nt < 8; nt++)
                    mma_fp16(acc[mt][nt], a[mt], &b[nt >> 1][(nt & 1) * 2]);
        }
    }

    #pragma unroll
    for (int mt = 0; mt < 2; mt++) {
        int rg = m0 + wm * 32 + mt * 16 + (lane >> 2);
        #pragma unroll
        for (int nt = 0; nt < 8; nt++) {
            int col = n0 + wn * 64 + nt * 8 + (lane & 3) * 2;
            float bb0 = b1[col] + b2[col];
            float bb1 = b1[col + 1] + b2[col + 1];
            __half2 p0 = *(const __half2*)&P[(size_t)rg * HH + col];
            __half2 p1 = *(const __half2*)&P[(size_t)(rg + 8) * HH + col];
            float2 pf0 = __half22float2(p0);
            float2 pf1 = __half22float2(p1);
            *(__half2*)&Cout[(size_t)rg * HH + col] =
                __floats2half2_rn(fmaxf(acc[mt][nt][0] + pf0.x + bb0, 0.f),
                                  fmaxf(acc[mt][nt][1] + pf0.y + bb1, 0.f));
            *(__half2*)&Cout[(size_t)(rg + 8) * HH + col] =
                __floats2half2_rn(fmaxf(acc[mt][nt][2] + pf1.x + bb0, 0.f),
                                  fmaxf(acc[mt][nt][3] + pf1.y + bb1, 0.f));
        }
    }
}

// ================= head_ab: a4/b4 = h2 @ w48[32:48]^T (N=16), K=512 ==========
#define HAB_B_TILE (16 * ROWB * 2)
#define HAB_BUF (TILE_BYTES + HAB_B_TILE)
#define HAB_SMEM_TOTAL (2 * HAB_BUF)

__global__ void __launch_bounds__(256) head_ab_kernel(
    const __half* __restrict__ A, const __half* __restrict__ B) {
    extern __shared__ char smem[];
    uint32_t sbase = smem_u32(smem);

    const int tid = threadIdx.x;
    const int lane = tid & 31, wid = tid >> 5;   // 8 warps, 16 M-rows each
    const int m0 = blockIdx.y * 128;

    const int sel = lane >> 3, lr = lane & 7;
    uint32_t a_off = (uint32_t)(((wid * 16 + (sel & 1) * 8 + lr) * ROWB
                                 + (sel >> 1) * 8) * 2);
    uint32_t b_off = (uint32_t)(TILE_BYTES
                     + (((sel >> 1) * 8 + lr) * ROWB + (sel & 1) * 8) * 2);

    float acc[2][4] = {};

    const int NCHUNK = 8;
    // prime: A 128 rows + B 16 rows
    stage_tile(sbase, A, m0, 0, HH, tid, 128);
    if (tid < 128) {
        int r = tid >> 3, c = tid & 7;
        cp16(sbase + TILE_BYTES + (uint32_t)(r * ROWB + c * 8) * 2,
             B + (size_t)r * HH + c * 8);
    }
    asm volatile("cp.async.commit_group;" ::: "memory");

    for (int it = 0; it < NCHUNK; ++it) {
        asm volatile("cp.async.wait_group 0;" ::: "memory");
        __syncthreads();
        if (it + 1 < NCHUNK) {
            int k0 = (it + 1) * 64;
            uint32_t nb = sbase + ((it + 1) & 1) * HAB_BUF;
            stage_tile(nb, A, m0, k0, HH, tid, 128);
            if (tid < 128) {
                int r = tid >> 3, c = tid & 7;
                cp16(nb + TILE_BYTES + (uint32_t)(r * ROWB + c * 8) * 2,
                     B + (size_t)r * HH + k0 + c * 8);
            }
            asm volatile("cp.async.commit_group;" ::: "memory");
        }
        uint32_t cbase = sbase + (it & 1) * HAB_BUF;
        #pragma unroll
        for (int ks = 0; ks < 4; ks++) {
            uint32_t a[4], b[4];
            ldmx4(a, cbase + a_off + ks * 32);
            ldmx4(b, cbase + b_off + ks * 32);
            #pragma unroll
            for (int nt = 0; nt < 2; nt++)
                mma_fp16(acc[nt], a, &b[nt * 2]);
        }
    }

    float* a4f = reinterpret_cast<float*>(g_a4);
    float* b4f = reinterpret_cast<float*>(g_b4);
    int rg = m0 + wid * 16 + (lane >> 2);
    #pragma unroll
    for (int nt = 0; nt < 2; nt++) {
        int col = nt * 8 + (lane & 3) * 2;
        #pragma unroll
        for (int half = 0; half < 2; half++) {
            int row = rg + half * 8;
            float v0 = acc[nt][half * 2 + 0];
            float v1 = acc[nt][half * 2 + 1];
            #pragma unroll
            for (int e = 0; e < 2; e++) {
                int c = col + e;
                float v = (e == 0) ? v0 : v1;
                if (c < 4)      a4f[row * 4 + c] = v;
                else if (c < 8) b4f[row * 4 + (c - 4)] = v;
            }
        }
    }
}

// ================= head_atom: atom logits only (side stream) =================
#define HD_TILE (64 * ROWB * 2)
#define HD_BUF (2 * HD_TILE)
#define HD_SMEM_TOTAL (2 * HD_BUF)

__global__ void __launch_bounds__(256) head_atom_kernel(
    const __half* __restrict__ A, const __half* __restrict__ B,
    const float* __restrict__ b_atom, float* __restrict__ atom_out) {
    extern __shared__ char smem[];
    uint32_t sbase = smem_u32(smem);

    const int tid = threadIdx.x;
    const int lane = tid & 31, wid = tid >> 5;
    const int wm = wid & 1, wn = wid >> 1;
    const int m0 = blockIdx.y * 64;

    const int sel = lane >> 3, lr = lane & 7;
    uint32_t a_off[2];
    #pragma unroll
    for (int mt = 0; mt < 2; mt++)
        a_off[mt] = (uint32_t)(((wm * 32 + mt * 16 + (sel & 1) * 8 + lr) * ROWB
                                + (sel >> 1) * 8) * 2);
    uint32_t b_off = (uint32_t)(HD_TILE
                     + ((wn * 16 + (sel >> 1) * 8 + lr) * ROWB + (sel & 1) * 8) * 2);

    float acc[2][2][4] = {};

    const int NCHUNK = 8;
    stage_tile(sbase, A, m0, 0, HH, tid, 64);
    stage_tile(sbase + HD_TILE, B, 0, 0, HH, tid, 64);
    asm volatile("cp.async.commit_group;" ::: "memory");

    for (int it = 0; it < NCHUNK; ++it) {
        asm volatile("cp.async.wait_group 0;" ::: "memory");
        __syncthreads();
        if (it + 1 < NCHUNK) {
            uint32_t nb = sbase + ((it + 1) & 1) * HD_BUF;
            stage_tile(nb, A, m0, (it + 1) * 64, HH, tid, 64);
            stage_tile(nb + HD_TILE, B, 0, (it + 1) * 64, HH, tid, 64);
            asm volatile("cp.async.commit_group;" ::: "memory");
        }

        uint32_t cbase = sbase + (it & 1) * HD_BUF;
        #pragma unroll
        for (int ks = 0; ks < 4; ks++) {
            uint32_t a[2][4], b[4];
            #pragma unroll
            for (int mt = 0; mt < 2; mt++)
                ldmx4(a[mt], cbase + a_off[mt] + ks * 32);
            ldmx4(b, cbase + b_off + ks * 32);
            #pragma unroll
            for (int mt = 0; mt < 2; mt++)
                #pragma unroll
                for (int nt = 0; nt < 2; nt++)
                    mma_fp16(acc[mt][nt], a[mt], &b[nt * 2]);
        }
    }

    #pragma unroll
    for (int mt = 0; mt < 2; mt++) {
        int rg = m0 + wm * 32 + mt * 16 + (lane >> 2);
        #pragma unroll
        for (int nt = 0; nt < 2; nt++) {
            int col = wn * 16 + nt * 8 + (lane & 3) * 2;
            if (col < 32) {
                #pragma unroll
                for (int half = 0; half < 2; half++) {
                    int row = rg + half * 8;
                    atom_out[row * FF + col] = acc[mt][nt][half * 2 + 0] + b_atom[col];
                    atom_out[row * FF + col + 1] = acc[mt][nt][half * 2 + 1] + b_atom[col + 1];
                }
            }
        }
    }
}

// ---------------- bond logits: 4 coalesced float4 per thread (proven) --------
__global__ void __launch_bounds__(256) bond_kernel(const float* __restrict__ b_bond,
                                                   float4* __restrict__ bond) {
    int i = blockIdx.y;
    int jbase = blockIdx.x * 1024 + threadIdx.x;
    float4 bb = make_float4(__ldg(&b_bond[0]), __ldg(&b_bond[1]),
                            __ldg(&b_bond[2]), __ldg(&b_bond[3]));
    float4 ai = g_a4[i];
    float4 bi = g_b4[i];
    float4 w[4];
    #pragma unroll
    for (int k = 0; k < 4; k++) {
        int j = jbase + k * 256;
        float4 r = make_float4(0.f, 0.f, 0.f, 0.f);
        if (i != j) {
            float4 av = (j < i) ? g_a4[j] : ai;
            float4 bv = (j < i) ? bi : g_b4[j];
            r.x = av.x + bv.x + bb.x;
            r.y = av.y + bv.y + bb.y;
            r.z = av.z + bv.z + bb.z;
            r.w = av.w + bv.w + bb.w;
        }
        w[k] = r;
    }
    #pragma unroll
    for (int k = 0; k < 4; k++)
        __stcs(&bond[(size_t)i * NN + jbase + k * 256], w[k]);
}

// ---------------- launch ----------------------------------------------------
extern "C" void kernel_launch(void* const* d_in, const int* in_sizes, int n_in,
                              void* d_out, int out_size) {
    const float* x        = (const float*)d_in[0];
    const float* adj      = (const float*)d_in[1];
    const float* w_self1  = (const float*)d_in[2];
    const float* b_self1  = (const float*)d_in[3];
    const float* w_neigh1 = (const float*)d_in[4];
    const float* b_neigh1 = (const float*)d_in[5];
    const float* w_self2  = (const float*)d_in[6];
    const float* b_self2  = (const float*)d_in[7];
    const float* w_neigh2 = (const float*)d_in[8];
    const float* b_neigh2 = (const float*)d_in[9];
    const float* w_atom   = (const float*)d_in[10];
    const float* b_atom   = (const float*)d_in[11];
    const float* w_bond   = (const float*)d_in[12];
    const float* b_bond   = (const float*)d_in[13];
    float* out = (float*)d_out;

    float* p_agg1p;
    __half* p_h2ph;
    __nv_bfloat16 *p_adjb, *p_h1T, *p_xTb;
    __half *p_h1h, *p_agg2h, *p_h2h, *p_ws2h, *p_wn2h, *p_w48h;
    cudaGetSymbolAddress((void**)&p_agg1p, g_agg1p);
    cudaGetSymbolAddress((void**)&p_h2ph,  g_h2ph);
    cudaGetSymbolAddress((void**)&p_adjb,  g_adjb);
    cudaGetSymbolAddress((void**)&p_h1T,   g_h1T);
    cudaGetSymbolAddress((void**)&p_xTb,   g_xTb);
    cudaGetSymbolAddress((void**)&p_h1h,   g_h1h);
    cudaGetSymbolAddress((void**)&p_agg2h, g_agg2h);
    cudaGetSymbolAddress((void**)&p_h2h,   g_h2h);
    cudaGetSymbolAddress((void**)&p_ws2h,  g_ws2h);
    cudaGetSymbolAddress((void**)&p_wn2h,  g_wn2h);
    cudaGetSymbolAddress((void**)&p_w48h,  g_w48h);

    cudaFuncSetAttribute(mma_agg1_kernel,
                         cudaFuncAttributeMaxDynamicSharedMemorySize, A1_SMEM_TOTAL);
    cudaFuncSetAttribute(mma_agg2_kernel,
                         cudaFuncAttributeMaxDynamicSharedMemorySize, A2_SMEM_TOTAL);
    cudaFuncSetAttribute(mma_gc2a_kernel,
                         cudaFuncAttributeMaxDynamicSharedMemorySize, MMA_SMEM_TOTAL);
    cudaFuncSetAttribute(mma_gc2b_kernel,
                         cudaFuncAttributeMaxDynamicSharedMemorySize, MMA_SMEM_TOTAL);
    cudaFuncSetAttribute(head_ab_kernel,
                         cudaFuncAttributeMaxDynamicSharedMemorySize, HAB_SMEM_TOTAL);
    cudaFuncSetAttribute(head_atom_kernel,
                         cudaFuncAttributeMaxDynamicSharedMemorySize, HD_SMEM_TOTAL);

    // static lowest-priority side stream + events
    static cudaStream_t s2 = nullptr;
    static cudaEvent_t evFork = nullptr, evJoin = nullptr;
    static cudaEvent_t evH = nullptr, evJ2 = nullptr;
    if (s2 == nullptr) {
        int leastPrio = 0, greatestPrio = 0;
        cudaDeviceGetStreamPriorityRange(&leastPrio, &greatestPrio);
        cudaStreamCreateWithPriority(&s2, cudaStreamNonBlocking, leastPrio);
        cudaEventCreateWithFlags(&evFork, cudaEventDisableTiming);
        cudaEventCreateWithFlags(&evJoin, cudaEventDisableTiming);
        cudaEventCreateWithFlags(&evH, cudaEventDisableTiming);
        cudaEventCreateWithFlags(&evJ2, cudaEventDisableTiming);
    }

    // 1. mega-prep
    megaprep_kernel<<<NN + 1152, 256>>>(adj, p_adjb, w_self2, w_neigh2,
                                        x, w_atom, w_bond);
    // 2. agg1 partials (K-split x16)
    mma_agg1_kernel<<<dim3(KSPLIT, NN / 128), 256, A1_SMEM_TOTAL>>>(
        p_adjb, p_xTb, p_agg1p);
    // 3. h1 layer
    fused_gc1_kernel<<<dim3(HH / 128, NN / 128), 256>>>(
        x, w_self1, b_self1, p_agg1p, w_neigh1, b_neigh1, p_h1T, p_h1h);

    // 4. agg2 FIRST on main stream; gc2a hidden on side stream
    cudaEventRecord(evFork, 0);
    mma_agg2_kernel<<<dim3(HH / 128, NN / 64), 256, A2_SMEM_TOTAL>>>(
        p_adjb, p_h1T, p_agg2h);
    cudaStreamWaitEvent(s2, evFork, 0);
    mma_gc2a_kernel<<<dim3(HH / 128, NN / 128), 256, MMA_SMEM_TOTAL, s2>>>(
        p_h1h, p_ws2h, p_h2ph);
    cudaEventRecord(evJoin, s2);
    cudaStreamWaitEvent(0, evJoin, 0);

    // 5. gc2b: h2 = relu(P + agg2@Wn2^T + b)
    mma_gc2b_kernel<<<dim3(HH / 128, NN / 128), 256, MMA_SMEM_TOTAL>>>(
        p_agg2h, p_wn2h, p_h2ph, b_self2, b_neigh2, p_h2h);

    // 6a. head_ab (a4/b4 only) on main stream — bond's sole dependency
    cudaEventRecord(evH, 0);
    head_ab_kernel<<<dim3(1, NN / 128), 256, HAB_SMEM_TOTAL>>>(
        p_h2h, p_w48h + 32 * HH);
    // 6b. head_atom on side stream, concurrent with bond
    cudaStreamWaitEvent(s2, evH, 0);
    head_atom_kernel<<<dim3(1, NN / 64), 256, HD_SMEM_TOTAL, s2>>>(
        p_h2h, p_w48h, b_atom, out);
    cudaEventRecord(evJ2, s2);

    // 7. bond logits (depends only on head_ab)
    bond_kernel<<<dim3(NN / 1024, NN), 256>>>(b_bond, (float4*)(out + (size_t)NN * FF));

    // join side stream before capture end
    cudaStreamWaitEvent(0, evJ2, 0);
}